// round 4
// baseline (speedup 1.0000x reference)
#include <cuda_runtime.h>
#include <cuda_bf16.h>
#include <cstdint>

// ---------------- problem geometry ----------------
#define T_TOK   4096
#define D_MODEL 4096
#define H_HEADS 32
#define DHEAD   128
#define B_SEQ   4
#define SQ      1024
#define HIST    1024
#define SKV     2048
#define NBLK    32
#define BS_PAGE 64
#define ATT_SCALE  0.08838834764831845f
#define INV_LN1024 0.14426950408889634f

// ---------------- scratch ----------------
__device__ float g_qkv[50331648];   // [T, 3*D]
__device__ float g_k  [33554432];   // [B,H,SKV,DH]
__device__ float g_v  [33554432];   // [B,H,SKV,DH]
__device__ float g_attn[16777216];  // [T, D]

// ---------------- helpers ----------------
__device__ __forceinline__ uint32_t f2tf32(float f) {
    uint32_t u;
    asm("cvt.rna.tf32.f32 %0, %1;" : "=r"(u) : "f"(f));
    return u;
}
__device__ __forceinline__ uint32_t pack2(__nv_bfloat16 a, __nv_bfloat16 b) {
    __nv_bfloat162 t = __nv_bfloat162(a, b);   // a -> low 16 bits
    return *reinterpret_cast<uint32_t*>(&t);
}
__device__ __forceinline__ void mma_bf16(float* c, const uint32_t* a, const uint32_t* b) {
    asm volatile(
        "mma.sync.aligned.m16n8k16.row.col.f32.bf16.bf16.f32 "
        "{%0,%1,%2,%3}, {%4,%5,%6,%7}, {%8,%9}, {%0,%1,%2,%3};"
        : "+f"(c[0]), "+f"(c[1]), "+f"(c[2]), "+f"(c[3])
        : "r"(a[0]), "r"(a[1]), "r"(a[2]), "r"(a[3]), "r"(b[0]), "r"(b[1]));
}
__device__ __forceinline__ void mma_tf32(float* c, const uint32_t* a, const uint32_t* b) {
    asm volatile(
        "mma.sync.aligned.m16n8k8.row.col.f32.tf32.tf32.f32 "
        "{%0,%1,%2,%3}, {%4,%5,%6,%7}, {%8,%9}, {%0,%1,%2,%3};"
        : "+f"(c[0]), "+f"(c[1]), "+f"(c[2]), "+f"(c[3])
        : "r"(a[0]), "r"(a[1]), "r"(a[2]), "r"(a[3]), "r"(b[0]), "r"(b[1]));
}
// exp(x) for x <= 0, FMA-pipe only (no MUFU). ~1e-7 rel err.
__device__ __forceinline__ float fast_exp(float x) {
    float y = fmaxf(x * 1.4426950408889634f, -126.f);
    float z = __fadd_rn(y, 12582912.f);          // rint via magic number
    int   n = __float_as_int(z) - 0x4B400000;    // n = rint(y)
    float f = y - __fsub_rn(z, 12582912.f);      // f in [-0.5, 0.5]
    float t = f * 0.6931471805599453f;
    float p = __fmaf_rn(t, 0.0013888889f, 0.0083333333f);
    p = __fmaf_rn(t, p, 0.0416666667f);
    p = __fmaf_rn(t, p, 0.1666666667f);
    p = __fmaf_rn(t, p, 0.5f);
    p = __fmaf_rn(t, p, 1.0f);
    p = __fmaf_rn(t, p, 1.0f);
    return p * __int_as_float((n + 127) << 23);
}

// =====================================================================
// bf16x3 GEMM: C = A@B (+bias). fp32-grade accuracy via Ootomo split:
// AhBh + AhBl + AlBh with bf16 m16n8k16. 128x128x32 tile, 2-stage smem.
// Smem (u32): AH[2][128][20], AL[2][128][20], BH[2][16][136], BL[2][16][136]
// =====================================================================
#define GEMM_SMEM_BYTES (18944 * 4)

__global__ __launch_bounds__(256) void bf16x3_gemm_kernel(
    const float* __restrict__ A, const float* __restrict__ Bm,
    const float* __restrict__ bias, float* __restrict__ C,
    int M, int N, int K)
{
    extern __shared__ uint32_t sg[];
    const int tid  = threadIdx.x;
    const int brow = blockIdx.y, bcol = blockIdx.x;
    const int warp = tid >> 5, lane = tid & 31;
    const int wr = warp >> 2, wc = warp & 3;
    const int gp = lane >> 2, q = lane & 3;

    float acc[4][4][4];
    #pragma unroll
    for (int mt = 0; mt < 4; mt++)
        #pragma unroll
        for (int nt = 0; nt < 4; nt++)
            #pragma unroll
            for (int r = 0; r < 4; r++) acc[mt][nt][r] = 0.f;

    const int arow = tid >> 1, akb = (tid & 1) << 4;      // A: row, k-base(0/16)
    const int bk2  = tid >> 4, bc8 = (tid & 15) << 3;     // B: k-pair idx, col-base
    const float* Ap  = A + (size_t)(brow * 128 + arow) * K + akb;
    const float* Bp0 = Bm + (size_t)(2 * bk2) * N + bcol * 128 + bc8;
    const float* Bp1 = Bp0 + N;

    float ae[16], be0[8], be1[8];

    auto load_regs = [&](int kt) {
        #pragma unroll
        for (int i = 0; i < 4; i++)
            *(float4*)&ae[4 * i] = *(const float4*)(Ap + kt + 4 * i);
        *(float4*)&be0[0] = *(const float4*)(Bp0 + (size_t)kt * N);
        *(float4*)&be0[4] = *(const float4*)(Bp0 + (size_t)kt * N + 4);
        *(float4*)&be1[0] = *(const float4*)(Bp1 + (size_t)kt * N);
        *(float4*)&be1[4] = *(const float4*)(Bp1 + (size_t)kt * N + 4);
    };

    auto store_tile = [&](int st) {
        uint32_t* AH = sg + st * 2560;
        uint32_t* AL = sg + 5120 + st * 2560;
        uint32_t* BH = sg + 10240 + st * 2176;
        uint32_t* BL = sg + 14592 + st * 2176;
        {   // A split: pairs along k
            uint32_t hi[8], lo[8];
            #pragma unroll
            for (int p = 0; p < 8; p++) {
                float f0 = ae[2 * p], f1 = ae[2 * p + 1];
                __nv_bfloat16 h0 = __float2bfloat16(f0);
                __nv_bfloat16 h1 = __float2bfloat16(f1);
                float r0 = f0 - __bfloat162float(h0);
                float r1 = f1 - __bfloat162float(h1);
                hi[p] = pack2(h0, h1);
                lo[p] = pack2(__float2bfloat16(r0), __float2bfloat16(r1));
            }
            const int kb2 = (tid & 1) << 3;
            *(uint4*)&AH[arow * 20 + kb2]     = *(uint4*)&hi[0];
            *(uint4*)&AH[arow * 20 + kb2 + 4] = *(uint4*)&hi[4];
            *(uint4*)&AL[arow * 20 + kb2]     = *(uint4*)&lo[0];
            *(uint4*)&AL[arow * 20 + kb2 + 4] = *(uint4*)&lo[4];
        }
        {   // B split: pack (k, k+1) of same column
            uint32_t hi[8], lo[8];
            #pragma unroll
            for (int j = 0; j < 8; j++) {
                float f0 = be0[j], f1 = be1[j];
                __nv_bfloat16 h0 = __float2bfloat16(f0);
                __nv_bfloat16 h1 = __float2bfloat16(f1);
                float r0 = f0 - __bfloat162float(h0);
                float r1 = f1 - __bfloat162float(h1);
                hi[j] = pack2(h0, h1);
                lo[j] = pack2(__float2bfloat16(r0), __float2bfloat16(r1));
            }
            *(uint4*)&BH[bk2 * 136 + bc8]     = *(uint4*)&hi[0];
            *(uint4*)&BH[bk2 * 136 + bc8 + 4] = *(uint4*)&hi[4];
            *(uint4*)&BL[bk2 * 136 + bc8]     = *(uint4*)&lo[0];
            *(uint4*)&BL[bk2 * 136 + bc8 + 4] = *(uint4*)&lo[4];
        }
    };

    load_regs(0);
    store_tile(0);
    __syncthreads();

    int buf = 0;
    for (int kt = 0; kt < K; kt += 32) {
        const bool more = (kt + 32 < K);
        if (more) load_regs(kt + 32);

        const uint32_t* AH = sg + buf * 2560;
        const uint32_t* AL = sg + 5120 + buf * 2560;
        const uint32_t* BH = sg + 10240 + buf * 2176;
        const uint32_t* BL = sg + 14592 + buf * 2176;

        #pragma unroll
        for (int ks = 0; ks < 2; ks++) {
            uint32_t bh[4][2], bl[4][2];
            #pragma unroll
            for (int nt = 0; nt < 4; nt++) {
                const int c = wc * 32 + nt * 8 + gp;
                bh[nt][0] = BH[(ks * 8 + q) * 136 + c];
                bh[nt][1] = BH[(ks * 8 + 4 + q) * 136 + c];
                bl[nt][0] = BL[(ks * 8 + q) * 136 + c];
                bl[nt][1] = BL[(ks * 8 + 4 + q) * 136 + c];
            }
            #pragma unroll
            for (int mt = 0; mt < 4; mt++) {
                const int r = wr * 64 + mt * 16;
                uint32_t ah[4], al[4];
                ah[0] = AH[(r + gp) * 20 + ks * 8 + q];
                ah[1] = AH[(r + gp + 8) * 20 + ks * 8 + q];
                ah[2] = AH[(r + gp) * 20 + ks * 8 + 4 + q];
                ah[3] = AH[(r + gp + 8) * 20 + ks * 8 + 4 + q];
                al[0] = AL[(r + gp) * 20 + ks * 8 + q];
                al[1] = AL[(r + gp + 8) * 20 + ks * 8 + q];
                al[2] = AL[(r + gp) * 20 + ks * 8 + 4 + q];
                al[3] = AL[(r + gp + 8) * 20 + ks * 8 + 4 + q];
                #pragma unroll
                for (int nt = 0; nt < 4; nt++) {
                    mma_bf16(acc[mt][nt], ah, bh[nt]);
                    mma_bf16(acc[mt][nt], ah, bl[nt]);
                    mma_bf16(acc[mt][nt], al, bh[nt]);
                }
            }
        }
        if (more) store_tile(buf ^ 1);
        __syncthreads();
        buf ^= 1;
    }

    // epilogue
    #pragma unroll
    for (int mt = 0; mt < 4; mt++) {
        const int r0 = brow * 128 + wr * 64 + mt * 16 + gp;
        #pragma unroll
        for (int nt = 0; nt < 4; nt++) {
            const int c0 = bcol * 128 + wc * 32 + nt * 8 + 2 * q;
            float bb0 = 0.f, bb1 = 0.f;
            if (bias) { bb0 = bias[c0]; bb1 = bias[c0 + 1]; }
            float2 v0, v1;
            v0.x = acc[mt][nt][0] + bb0; v0.y = acc[mt][nt][1] + bb1;
            v1.x = acc[mt][nt][2] + bb0; v1.y = acc[mt][nt][3] + bb1;
            *(float2*)&C[(size_t)r0 * N + c0]       = v0;
            *(float2*)&C[(size_t)(r0 + 8) * N + c0] = v1;
        }
    }
}

// =====================================================================
// RoPE + logn on Q in place.
// =====================================================================
__global__ void rope_q_kernel(float* __restrict__ qkv,
                              const float* __restrict__ cosT,
                              const float* __restrict__ sinT)
{
    const int t = blockIdx.x, h = blockIdx.y, d = threadIdx.x;
    const int pos = HIST + (t & (SQ - 1));
    const float logn = logf((float)(pos + 1)) * INV_LN1024;
    float* qp = qkv + (size_t)t * (3 * D_MODEL) + h * DHEAD;
    const float c1 = cosT[(size_t)pos * DHEAD + d];
    const float c2 = cosT[(size_t)pos * DHEAD + d + 64];
    const float s1 = sinT[(size_t)pos * DHEAD + d];
    const float s2 = sinT[(size_t)pos * DHEAD + d + 64];
    const float q1 = qp[d], q2 = qp[d + 64];
    qp[d]      = (q1 * c1 - q2 * s1) * logn;
    qp[d + 64] = (q2 * c2 + q1 * s2) * logn;
}

// =====================================================================
// Build contiguous K/V [B,H,SKV,DH].
// =====================================================================
__global__ void build_kv_kernel(const float* __restrict__ qkv,
                                const float* __restrict__ kcache,
                                const float* __restrict__ vcache,
                                const int* __restrict__ blockOff,
                                const float* __restrict__ cosT,
                                const float* __restrict__ sinT,
                                float* __restrict__ Kout,
                                float* __restrict__ Vout)
{
    const int s = blockIdx.x, b = blockIdx.y, d = threadIdx.x;
    if (s < HIST) {
        const int blk = blockOff[b * NBLK + (s >> 6)];
        const size_t src = ((size_t)(blk * BS_PAGE + (s & 63))) * H_HEADS * DHEAD;
        for (int h = 0; h < H_HEADS; h++) {
            const size_t dst = (((size_t)(b * H_HEADS + h)) * SKV + s) * DHEAD + d;
            Kout[dst] = kcache[src + h * DHEAD + d];
            Vout[dst] = vcache[src + h * DHEAD + d];
        }
    } else {
        const int t = b * SQ + (s - HIST);
        const int pos = s;
        const float c  = cosT[(size_t)pos * DHEAD + d];
        const float sn = sinT[(size_t)pos * DHEAD + d];
        const float* kp = qkv + (size_t)t * (3 * D_MODEL) + D_MODEL;
        const float* vp = kp + D_MODEL;
        for (int h = 0; h < H_HEADS; h++) {
            const float k1 = kp[h * DHEAD + d];
            const float rot = (d < 64) ? -kp[h * DHEAD + d + 64]
                                       :  kp[h * DHEAD + d - 64];
            const size_t dst = (((size_t)(b * H_HEADS + h)) * SKV + s) * DHEAD + d;
            Kout[dst] = k1 * c + rot * sn;
            Vout[dst] = vp[h * DHEAD + d];
        }
    }
}

// =====================================================================
// Flash attention, tf32 tensor cores. One block per (b*h, 64-q-tile).
// Smem (u32): Qs[64][132], Kt[128][72], Vs[64][136], Ps[64][68], stats.
// S phase: warps 2x4 (32x16 each). PV phase: warps 4x2 (16x64 each).
// =====================================================================
#define FL_SMEM_U32 (64*132 + 128*72 + 64*136 + 64*68 + 192)
#define FL_SMEM_BYTES (FL_SMEM_U32 * 4)

__global__ __launch_bounds__(256) void flash_tc_kernel(
    const float* __restrict__ Qg,
    const float* __restrict__ Kg,
    const float* __restrict__ Vg,
    float* __restrict__ Og)
{
    extern __shared__ uint32_t fsm[];
    uint32_t* Qs = fsm;                  // [64][132]
    uint32_t* Kt = Qs + 64 * 132;        // [128][72]  (transposed K: [d][s])
    uint32_t* Vs = Kt + 128 * 72;        // [64][136]
    uint32_t* Ps = Vs + 64 * 136;        // [64][68]
    float* m_s = (float*)(Ps + 64 * 68);
    float* l_s = m_s + 64;
    float* c_s = l_s + 64;
    float* Psf = (float*)Ps;

    const int bh = blockIdx.x;
    const int b = bh >> 5, h = bh & 31;
    const int q0 = blockIdx.y * 64;
    const int tid = threadIdx.x;
    const int warp = tid >> 5, lane = tid & 31;
    const int gp = lane >> 2, q = lane & 3;
    const int wr = warp >> 2, wc = warp & 3;     // S phase 2x4
    const int wor = warp >> 1, woc = warp & 1;   // PV phase 4x2

    // load Q tile as tf32
    for (int idx = tid; idx < 64 * 32; idx += 256) {
        const int r = idx >> 5, d4 = (idx & 31) << 2;
        const int t = b * SQ + q0 + r;
        float4 v = *(const float4*)&Qg[(size_t)t * (3 * D_MODEL) + h * DHEAD + d4];
        uint4 u;
        u.x = f2tf32(v.x); u.y = f2tf32(v.y); u.z = f2tf32(v.z); u.w = f2tf32(v.w);
        *(uint4*)&Qs[r * 132 + d4] = u;
    }
    if (tid < 64) { m_s[tid] = -1e30f; l_s[tid] = 0.f; }

    float oacc[8][4];
    #pragma unroll
    for (int nt = 0; nt < 8; nt++)
        { oacc[nt][0] = 0.f; oacc[nt][1] = 0.f; oacc[nt][2] = 0.f; oacc[nt][3] = 0.f; }

    const float* Kbh = Kg + (size_t)bh * SKV * DHEAD;
    const float* Vbh = Vg + (size_t)bh * SKV * DHEAD;
    const int ntiles = (HIST + q0) / 64 + 1;
    __syncthreads();

    for (int kt = 0; kt < ntiles; kt++) {
        const int s0 = kt * 64;
        // load K (transposed) + V tiles as tf32
        for (int idx = tid; idx < 64 * 32; idx += 256) {
            const int s = idx >> 5, d4 = (idx & 31) << 2;
            float4 kv = *(const float4*)&Kbh[(size_t)(s0 + s) * DHEAD + d4];
            Kt[(d4 + 0) * 72 + s] = f2tf32(kv.x);
            Kt[(d4 + 1) * 72 + s] = f2tf32(kv.y);
            Kt[(d4 + 2) * 72 + s] = f2tf32(kv.z);
            Kt[(d4 + 3) * 72 + s] = f2tf32(kv.w);
            float4 vv = *(const float4*)&Vbh[(size_t)(s0 + s) * DHEAD + d4];
            uint4 u;
            u.x = f2tf32(vv.x); u.y = f2tf32(vv.y); u.z = f2tf32(vv.z); u.w = f2tf32(vv.w);
            *(uint4*)&Vs[s * 136 + d4] = u;
        }
        __syncthreads();

        // ---- S = Q @ K^T ----
        float sacc[2][2][4];
        #pragma unroll
        for (int mt = 0; mt < 2; mt++)
            #pragma unroll
            for (int nt = 0; nt < 2; nt++)
                #pragma unroll
                for (int r = 0; r < 4; r++) sacc[mt][nt][r] = 0.f;

        #pragma unroll
        for (int ks = 0; ks < 16; ks++) {
            const int k0 = ks * 8;
            uint32_t bb[2][2];
            #pragma unroll
            for (int nt = 0; nt < 2; nt++) {
                const int c = wc * 16 + nt * 8 + gp;
                bb[nt][0] = Kt[(k0 + q) * 72 + c];
                bb[nt][1] = Kt[(k0 + 4 + q) * 72 + c];
            }
            #pragma unroll
            for (int mt = 0; mt < 2; mt++) {
                const int r = wr * 32 + mt * 16;
                uint32_t aa[4];
                aa[0] = Qs[(r + gp) * 132 + k0 + q];
                aa[1] = Qs[(r + gp + 8) * 132 + k0 + q];
                aa[2] = Qs[(r + gp) * 132 + k0 + 4 + q];
                aa[3] = Qs[(r + gp + 8) * 132 + k0 + 4 + q];
                #pragma unroll
                for (int nt = 0; nt < 2; nt++)
                    mma_tf32(sacc[mt][nt], aa, bb[nt]);
            }
        }

        // scale + causal mask (only last tile is diagonal) + write scores
        const bool lastt = (kt == ntiles - 1);
        #pragma unroll
        for (int mt = 0; mt < 2; mt++) {
            const int r = wr * 32 + mt * 16 + gp;
            #pragma unroll
            for (int nt = 0; nt < 2; nt++) {
                const int c = wc * 16 + nt * 8 + 2 * q;
                float v0 = sacc[mt][nt][0] * ATT_SCALE;
                float v1 = sacc[mt][nt][1] * ATT_SCALE;
                float v2 = sacc[mt][nt][2] * ATT_SCALE;
                float v3 = sacc[mt][nt][3] * ATT_SCALE;
                if (lastt) {
                    if (c     > r)     v0 = -1e30f;
                    if (c + 1 > r)     v1 = -1e30f;
                    if (c     > r + 8) v2 = -1e30f;
                    if (c + 1 > r + 8) v3 = -1e30f;
                }
                Psf[r * 68 + c] = v0;       Psf[r * 68 + c + 1] = v1;
                Psf[(r + 8) * 68 + c] = v2; Psf[(r + 8) * 68 + c + 1] = v3;
            }
        }
        __syncthreads();

        // ---- online softmax (4 threads per row); write probs as tf32 ----
        {
            const int row = tid >> 2, q2 = tid & 3;
            float* prow = Psf + row * 68 + q2 * 16;
            uint32_t* prow_u = (uint32_t*)prow;
            float mx = -1e30f;
            #pragma unroll
            for (int k = 0; k < 16; k++) mx = fmaxf(mx, prow[k]);
            mx = fmaxf(mx, __shfl_xor_sync(0xffffffffu, mx, 1));
            mx = fmaxf(mx, __shfl_xor_sync(0xffffffffu, mx, 2));
            const float m_old = m_s[row];
            const float m_new = fmaxf(m_old, mx);
            float ssum = 0.f;
            #pragma unroll
            for (int k = 0; k < 16; k++) {
                const float p = fast_exp(prow[k] - m_new);
                prow_u[k] = f2tf32(p);
                ssum += p;
            }
            ssum += __shfl_xor_sync(0xffffffffu, ssum, 1);
            ssum += __shfl_xor_sync(0xffffffffu, ssum, 2);
            if (q2 == 0) {
                const float corr = fast_exp(m_old - m_new);
                l_s[row] = l_s[row] * corr + ssum;
                m_s[row] = m_new;
                c_s[row] = corr;
            }
        }
        __syncthreads();

        // ---- O = O*corr + P @ V ----
        {
            const float c0 = c_s[wor * 16 + gp];
            const float c1 = c_s[wor * 16 + gp + 8];
            #pragma unroll
            for (int nt = 0; nt < 8; nt++) {
                oacc[nt][0] *= c0; oacc[nt][1] *= c0;
                oacc[nt][2] *= c1; oacc[nt][3] *= c1;
            }
        }
        #pragma unroll
        for (int ks = 0; ks < 8; ks++) {
            const int k0 = ks * 8;
            uint32_t aa[4];
            const int r = wor * 16;
            aa[0] = Ps[(r + gp) * 68 + k0 + q];
            aa[1] = Ps[(r + gp + 8) * 68 + k0 + q];
            aa[2] = Ps[(r + gp) * 68 + k0 + 4 + q];
            aa[3] = Ps[(r + gp + 8) * 68 + k0 + 4 + q];
            #pragma unroll
            for (int nt = 0; nt < 8; nt++) {
                const int cN = woc * 64 + nt * 8 + gp;
                uint32_t bb[2];
                bb[0] = Vs[(k0 + q) * 136 + cN];
                bb[1] = Vs[(k0 + 4 + q) * 136 + cN];
                mma_tf32(oacc[nt], aa, bb);
            }
        }
        __syncthreads();
    }

    // epilogue
    {
        const int r = wor * 16 + gp;
        const float inv0 = 1.f / l_s[r];
        const float inv1 = 1.f / l_s[r + 8];
        const int t0 = b * SQ + q0 + r;
        #pragma unroll
        for (int nt = 0; nt < 8; nt++) {
            const int c = woc * 64 + nt * 8 + 2 * q;
            float2 w0, w1;
            w0.x = oacc[nt][0] * inv0; w0.y = oacc[nt][1] * inv0;
            w1.x = oacc[nt][2] * inv1; w1.y = oacc[nt][3] * inv1;
            *(float2*)&Og[(size_t)t0 * D_MODEL + h * DHEAD + c]       = w0;
            *(float2*)&Og[(size_t)(t0 + 8) * D_MODEL + h * DHEAD + c] = w1;
        }
    }
}

// =====================================================================
// launch
// =====================================================================
extern "C" void kernel_launch(void* const* d_in, const int* in_sizes, int n_in,
                              void* d_out, int out_size)
{
    const float* hidden  = (const float*)d_in[0];
    const float* w_qkv   = (const float*)d_in[1];
    const float* b_qkv   = (const float*)d_in[2];
    const float* w_proj  = (const float*)d_in[3];
    const float* cosT    = (const float*)d_in[4];
    const float* sinT    = (const float*)d_in[5];
    const float* kcache  = (const float*)d_in[6];
    const float* vcache  = (const float*)d_in[7];
    const int*   blkOff  = (const int*)d_in[8];
    float* out = (float*)d_out;

    float *qkv_p, *k_p, *v_p, *attn_p;
    cudaGetSymbolAddress((void**)&qkv_p,  g_qkv);
    cudaGetSymbolAddress((void**)&k_p,    g_k);
    cudaGetSymbolAddress((void**)&v_p,    g_v);
    cudaGetSymbolAddress((void**)&attn_p, g_attn);

    cudaFuncSetAttribute(bf16x3_gemm_kernel,
                         cudaFuncAttributeMaxDynamicSharedMemorySize,
                         GEMM_SMEM_BYTES);
    cudaFuncSetAttribute(flash_tc_kernel,
                         cudaFuncAttributeMaxDynamicSharedMemorySize,
                         FL_SMEM_BYTES);

    // 1) QKV projection
    bf16x3_gemm_kernel<<<dim3(3 * D_MODEL / 128, T_TOK / 128), 256,
                         GEMM_SMEM_BYTES>>>(
        hidden, w_qkv, b_qkv, qkv_p, T_TOK, 3 * D_MODEL, D_MODEL);

    // 2) RoPE + logn on Q
    rope_q_kernel<<<dim3(T_TOK, H_HEADS), 64>>>(qkv_p, cosT, sinT);

    // 3) build contiguous K/V
    build_kv_kernel<<<dim3(SKV, B_SEQ), 128>>>(
        qkv_p, kcache, vcache, blkOff, cosT, sinT, k_p, v_p);

    // 4) causal flash attention (tensor cores)
    flash_tc_kernel<<<dim3(B_SEQ * H_HEADS, SQ / 64), 256, FL_SMEM_BYTES>>>(
        qkv_p, k_p, v_p, attn_p);

    // 5) output projection
    bf16x3_gemm_kernel<<<dim3(D_MODEL / 128, T_TOK / 128), 256,
                         GEMM_SMEM_BYTES>>>(
        attn_p, w_proj, nullptr, out, T_TOK, D_MODEL, D_MODEL);
}

// round 6
// speedup vs baseline: 1.1896x; 1.1896x over previous
#include <cuda_runtime.h>
#include <cuda_bf16.h>
#include <cstdint>

// ---------------- problem geometry ----------------
#define T_TOK   4096
#define D_MODEL 4096
#define H_HEADS 32
#define DHEAD   128
#define B_SEQ   4
#define SQ      1024
#define HIST    1024
#define SKV     2048
#define NBLK    32
#define BS_PAGE 64
#define ATT_SCALE  0.08838834764831845f
#define INV_LN1024 0.14426950408889634f

// ---------------- scratch ----------------
__device__ float g_qkv[50331648];   // [T, 3*D]
__device__ float g_k  [33554432];   // [B,H,SKV,DH]
__device__ float g_v  [33554432];   // [B,H,SKV,DH]
__device__ float g_attn[16777216];  // [T, D]

// ---------------- helpers ----------------
__device__ __forceinline__ uint32_t f2tf32(float f) {
    uint32_t u;
    asm("cvt.rna.tf32.f32 %0, %1;" : "=r"(u) : "f"(f));
    return u;
}
__device__ __forceinline__ uint32_t pack2(__nv_bfloat16 a, __nv_bfloat16 b) {
    __nv_bfloat162 t = __nv_bfloat162(a, b);   // a -> low 16 bits (k even)
    return *reinterpret_cast<uint32_t*>(&t);
}
__device__ __forceinline__ void split_bf16(float f, __nv_bfloat16& h, __nv_bfloat16& l) {
    h = __float2bfloat16(f);
    l = __float2bfloat16(f - __bfloat162float(h));
}
__device__ __forceinline__ void mma_bf16(float* c, const uint32_t* a, const uint32_t* b) {
    asm volatile(
        "mma.sync.aligned.m16n8k16.row.col.f32.bf16.bf16.f32 "
        "{%0,%1,%2,%3}, {%4,%5,%6,%7}, {%8,%9}, {%0,%1,%2,%3};"
        : "+f"(c[0]), "+f"(c[1]), "+f"(c[2]), "+f"(c[3])
        : "r"(a[0]), "r"(a[1]), "r"(a[2]), "r"(a[3]), "r"(b[0]), "r"(b[1]));
}
__device__ __forceinline__ void mma_tf32(float* c, const uint32_t* a, const uint32_t* b) {
    asm volatile(
        "mma.sync.aligned.m16n8k8.row.col.f32.tf32.tf32.f32 "
        "{%0,%1,%2,%3}, {%4,%5,%6,%7}, {%8,%9}, {%0,%1,%2,%3};"
        : "+f"(c[0]), "+f"(c[1]), "+f"(c[2]), "+f"(c[3])
        : "r"(a[0]), "r"(a[1]), "r"(a[2]), "r"(a[3]), "r"(b[0]), "r"(b[1]));
}
// exp(x) for x <= 0, FMA-pipe only. ~1e-7 rel err.
__device__ __forceinline__ float fast_exp(float x) {
    float y = fmaxf(x * 1.4426950408889634f, -126.f);
    float z = __fadd_rn(y, 12582912.f);
    int   n = __float_as_int(z) - 0x4B400000;
    float f = y - __fsub_rn(z, 12582912.f);
    float t = f * 0.6931471805599453f;
    float p = __fmaf_rn(t, 0.0013888889f, 0.0083333333f);
    p = __fmaf_rn(t, p, 0.0416666667f);
    p = __fmaf_rn(t, p, 0.1666666667f);
    p = __fmaf_rn(t, p, 0.5f);
    p = __fmaf_rn(t, p, 1.0f);
    p = __fmaf_rn(t, p, 1.0f);
    return p * __int_as_float((n + 127) << 23);
}

// =====================================================================
// TF32 GEMM, double-buffered: C[M,N] = A[M,K] @ B[K,N] (+bias)
// 128x128x32 tile, 8 warps (2x4), warp tile 64x32, m16n8k8 tf32.
// smem (u32): As[2][128][36], Bs[2][32][136]  = 71680 B
// =====================================================================
#define G_SMEM_BYTES (17920 * 4)

__global__ __launch_bounds__(256, 2) void tf32_gemm_kernel(
    const float* __restrict__ A, const float* __restrict__ Bm,
    const float* __restrict__ bias, float* __restrict__ C,
    int M, int N, int K)
{
    extern __shared__ uint32_t sg[];
    uint32_t* AsB[2] = { sg,        sg + 4608 };
    uint32_t* BsB[2] = { sg + 9216, sg + 13568 };

    const int tid  = threadIdx.x;
    const int brow = blockIdx.y, bcol = blockIdx.x;
    const int warp = tid >> 5, lane = tid & 31;
    const int wr = warp >> 2, wc = warp & 3;
    const int gp = lane >> 2, q = lane & 3;

    float acc[4][4][4];
    #pragma unroll
    for (int mt = 0; mt < 4; mt++)
        #pragma unroll
        for (int nt = 0; nt < 4; nt++)
            #pragma unroll
            for (int r = 0; r < 4; r++) acc[mt][nt][r] = 0.f;

    const float* Ab = A + (size_t)(brow * 128) * K;
    const float* Bb = Bm + (size_t)bcol * 128;

    float4 av[4], bv[4];
    auto load_regs = [&](int kt) {
        #pragma unroll
        for (int i = 0; i < 4; i++) {
            const int u = tid + 256 * i;
            av[i] = *(const float4*)(Ab + (size_t)(u >> 3) * K + kt + ((u & 7) << 2));
            bv[i] = *(const float4*)(Bb + (size_t)(kt + (u >> 5)) * N + ((u & 31) << 2));
        }
    };
    auto store_stage = [&](int st) {
        uint32_t* As = AsB[st];
        uint32_t* Bs = BsB[st];
        #pragma unroll
        for (int i = 0; i < 4; i++) {
            const int u = tid + 256 * i;
            uint4 ta, tb;
            ta.x = f2tf32(av[i].x); ta.y = f2tf32(av[i].y);
            ta.z = f2tf32(av[i].z); ta.w = f2tf32(av[i].w);
            tb.x = f2tf32(bv[i].x); tb.y = f2tf32(bv[i].y);
            tb.z = f2tf32(bv[i].z); tb.w = f2tf32(bv[i].w);
            *(uint4*)&As[(u >> 3) * 36 + ((u & 7) << 2)]   = ta;
            *(uint4*)&Bs[(u >> 5) * 136 + ((u & 31) << 2)] = tb;
        }
    };

    load_regs(0);
    store_stage(0);
    __syncthreads();

    for (int kt = 0; kt < K; kt += 32) {
        const int buf = (kt >> 5) & 1;
        const bool more = (kt + 32 < K);
        if (more) load_regs(kt + 32);

        const uint32_t* As = AsB[buf];
        const uint32_t* Bs = BsB[buf];
        #pragma unroll
        for (int kk = 0; kk < 32; kk += 8) {
            uint32_t af[4][4], bf[4][2];
            #pragma unroll
            for (int mt = 0; mt < 4; mt++) {
                const int r = wr * 64 + mt * 16 + gp;
                af[mt][0] = As[r * 36 + kk + q];
                af[mt][1] = As[(r + 8) * 36 + kk + q];
                af[mt][2] = As[r * 36 + kk + q + 4];
                af[mt][3] = As[(r + 8) * 36 + kk + q + 4];
            }
            #pragma unroll
            for (int nt = 0; nt < 4; nt++) {
                const int c = wc * 32 + nt * 8 + gp;
                bf[nt][0] = Bs[(kk + q) * 136 + c];
                bf[nt][1] = Bs[(kk + q + 4) * 136 + c];
            }
            #pragma unroll
            for (int mt = 0; mt < 4; mt++)
                #pragma unroll
                for (int nt = 0; nt < 4; nt++)
                    mma_tf32(acc[mt][nt], af[mt], bf[nt]);
        }
        if (more) store_stage(buf ^ 1);
        __syncthreads();
    }

    #pragma unroll
    for (int mt = 0; mt < 4; mt++) {
        const int r0 = brow * 128 + wr * 64 + mt * 16 + gp;
        #pragma unroll
        for (int nt = 0; nt < 4; nt++) {
            const int c0 = bcol * 128 + wc * 32 + nt * 8 + 2 * q;
            float bb0 = 0.f, bb1 = 0.f;
            if (bias) { bb0 = bias[c0]; bb1 = bias[c0 + 1]; }
            float2 v0, v1;
            v0.x = acc[mt][nt][0] + bb0; v0.y = acc[mt][nt][1] + bb1;
            v1.x = acc[mt][nt][2] + bb0; v1.y = acc[mt][nt][3] + bb1;
            *(float2*)&C[(size_t)r0 * N + c0]       = v0;
            *(float2*)&C[(size_t)(r0 + 8) * N + c0] = v1;
        }
    }
}

// =====================================================================
// Build contiguous K/V [B,H,SKV,DH].
// =====================================================================
__global__ void build_kv_kernel(const float* __restrict__ qkv,
                                const float* __restrict__ kcache,
                                const float* __restrict__ vcache,
                                const int* __restrict__ blockOff,
                                const float* __restrict__ cosT,
                                const float* __restrict__ sinT,
                                float* __restrict__ Kout,
                                float* __restrict__ Vout)
{
    const int s = blockIdx.x, b = blockIdx.y, d = threadIdx.x;
    if (s < HIST) {
        const int blk = blockOff[b * NBLK + (s >> 6)];
        const size_t src = ((size_t)(blk * BS_PAGE + (s & 63))) * H_HEADS * DHEAD;
        for (int h = 0; h < H_HEADS; h++) {
            const size_t dst = (((size_t)(b * H_HEADS + h)) * SKV + s) * DHEAD + d;
            Kout[dst] = kcache[src + h * DHEAD + d];
            Vout[dst] = vcache[src + h * DHEAD + d];
        }
    } else {
        const int t = b * SQ + (s - HIST);
        const int pos = s;
        const float c  = cosT[(size_t)pos * DHEAD + d];
        const float sn = sinT[(size_t)pos * DHEAD + d];
        const float* kp = qkv + (size_t)t * (3 * D_MODEL) + D_MODEL;
        const float* vp = kp + D_MODEL;
        for (int h = 0; h < H_HEADS; h++) {
            const float k1 = kp[h * DHEAD + d];
            const float rot = (d < 64) ? -kp[h * DHEAD + d + 64]
                                       :  kp[h * DHEAD + d - 64];
            const size_t dst = (((size_t)(b * H_HEADS + h)) * SKV + s) * DHEAD + d;
            Kout[dst] = k1 * c + rot * sn;
            Vout[dst] = vp[h * DHEAD + d];
        }
    }
}

// =====================================================================
// Flash attention v2, bf16x3 numerics on mma.sync tensor cores.
// CTA: 512 threads, q-tile 128, fused RoPE+logn on Q load.
// smem layout (u32 offsets):
//   QH 0        [128][68]     QL 8704
//   KH 17408    [64][68]      KL 21760
//   VTH 26112   [128][33]     VTL 30336   (V transposed: [d][s-pair])
//   SF 34560    [128][68] f32
//   PH 43264    [128][36]     PL 47872
//   STATS 52480 (m 128, l 128, c 128)
// total 52864 u32 = 211456 B
// =====================================================================
#define FL_QH   0
#define FL_QL   8704
#define FL_KH   17408
#define FL_KL   21760
#define FL_VTH  26112
#define FL_VTL  30336
#define FL_SF   34560
#define FL_PH   43264
#define FL_PL   47872
#define FL_ST   52480
#define FL_SMEM_BYTES (52864 * 4)

__global__ __launch_bounds__(512) void flash_v2_kernel(
    const float* __restrict__ Qg,   // g_qkv (raw q section; RoPE applied here)
    const float* __restrict__ Kg,
    const float* __restrict__ Vg,
    const float* __restrict__ cosT,
    const float* __restrict__ sinT,
    float* __restrict__ Og)
{
    extern __shared__ uint32_t fsm[];
    uint32_t* QH  = fsm + FL_QH;
    uint32_t* QL  = fsm + FL_QL;
    uint32_t* KH  = fsm + FL_KH;
    uint32_t* KL  = fsm + FL_KL;
    uint32_t* VTH = fsm + FL_VTH;
    uint32_t* VTL = fsm + FL_VTL;
    float*    SF  = (float*)(fsm + FL_SF);
    uint32_t* PH  = fsm + FL_PH;
    uint32_t* PL  = fsm + FL_PL;
    float* m_s = (float*)(fsm + FL_ST);
    float* l_s = m_s + 128;
    float* c_s = l_s + 128;

    const int bh = blockIdx.x;
    const int b = bh >> 5, h = bh & 31;
    const int q0 = blockIdx.y * 128;
    const int tid = threadIdx.x;
    const int warp = tid >> 5, lane = tid & 31;
    const int gp = lane >> 2, q = lane & 3;
    const int wr = warp >> 2, wc = warp & 3;     // S phase: 4x4 warps
    const int wor = warp >> 1, woc = warp & 1;   // PV phase: 8x2 warps

    // ---- load Q tile + RoPE + logn + bf16 split ----
    {
        const int row = tid >> 2;
        const int d0  = (tid & 3) * 16;
        const int t   = b * SQ + q0 + row;
        const int pos = HIST + q0 + row;
        const float logn = logf((float)(pos + 1)) * INV_LN1024;
        const float* qrow = Qg + (size_t)t * (3 * D_MODEL) + h * DHEAD;
        const float* crow = cosT + (size_t)pos * DHEAD;
        const float* srow = sinT + (size_t)pos * DHEAD;
        float qa[16], qb[16], ca[16], cb[16], sa[16], sb[16];
        #pragma unroll
        for (int i = 0; i < 4; i++) {
            *(float4*)&qa[4*i] = *(const float4*)(qrow + d0 + 4*i);
            *(float4*)&qb[4*i] = *(const float4*)(qrow + d0 + 64 + 4*i);
            *(float4*)&ca[4*i] = *(const float4*)(crow + d0 + 4*i);
            *(float4*)&cb[4*i] = *(const float4*)(crow + d0 + 64 + 4*i);
            *(float4*)&sa[4*i] = *(const float4*)(srow + d0 + 4*i);
            *(float4*)&sb[4*i] = *(const float4*)(srow + d0 + 64 + 4*i);
        }
        #pragma unroll
        for (int j = 0; j < 8; j++) {       // pairs within each 16-wide range
            float f0 = (qa[2*j]   * ca[2*j]   - qb[2*j]   * sa[2*j])   * logn;
            float f1 = (qa[2*j+1] * ca[2*j+1] - qb[2*j+1] * sa[2*j+1]) * logn;
            float g0 = (qb[2*j]   * cb[2*j]   + qa[2*j]   * sb[2*j])   * logn;
            float g1 = (qb[2*j+1] * cb[2*j+1] + qa[2*j+1] * sb[2*j+1]) * logn;
            __nv_bfloat16 h0, l0, h1, l1;
            split_bf16(f0, h0, l0); split_bf16(f1, h1, l1);
            QH[row * 68 + d0/2 + j] = pack2(h0, h1);
            QL[row * 68 + d0/2 + j] = pack2(l0, l1);
            split_bf16(g0, h0, l0); split_bf16(g1, h1, l1);
            QH[row * 68 + (d0 + 64)/2 + j] = pack2(h0, h1);
            QL[row * 68 + (d0 + 64)/2 + j] = pack2(l0, l1);
        }
    }
    if (tid < 128) { m_s[tid] = -1e30f; l_s[tid] = 0.f; }

    float oacc[8][4];
    #pragma unroll
    for (int nt = 0; nt < 8; nt++)
        { oacc[nt][0]=0.f; oacc[nt][1]=0.f; oacc[nt][2]=0.f; oacc[nt][3]=0.f; }

    const float* Kbh = Kg + (size_t)bh * SKV * DHEAD;
    const float* Vbh = Vg + (size_t)bh * SKV * DHEAD;
    const int ntiles = (HIST + q0 + 128) / 64;
    __syncthreads();

    for (int kt = 0; kt < ntiles; kt++) {
        const int s0 = kt * 64;
        // ---- load K tile (bf16 split, [s][d-pair]) ----
        {
            const int s  = tid >> 3;
            const int d0 = (tid & 7) * 16;
            float kf[16];
            #pragma unroll
            for (int i = 0; i < 4; i++)
                *(float4*)&kf[4*i] = *(const float4*)(Kbh + (size_t)(s0 + s) * DHEAD + d0 + 4*i);
            #pragma unroll
            for (int j = 0; j < 8; j++) {
                __nv_bfloat16 h0, l0, h1, l1;
                split_bf16(kf[2*j],   h0, l0);
                split_bf16(kf[2*j+1], h1, l1);
                KH[s * 68 + d0/2 + j] = pack2(h0, h1);
                KL[s * 68 + d0/2 + j] = pack2(l0, l1);
            }
        }
        // ---- load V tile transposed (bf16 split, [d][s-pair]) ----
        {
            const int sp = tid >> 4;            // 0..31 s-pairs
            const int d0 = (tid & 15) * 8;
            float v0[8], v1[8];
            *(float4*)&v0[0] = *(const float4*)(Vbh + (size_t)(s0 + 2*sp)     * DHEAD + d0);
            *(float4*)&v0[4] = *(const float4*)(Vbh + (size_t)(s0 + 2*sp)     * DHEAD + d0 + 4);
            *(float4*)&v1[0] = *(const float4*)(Vbh + (size_t)(s0 + 2*sp + 1) * DHEAD + d0);
            *(float4*)&v1[4] = *(const float4*)(Vbh + (size_t)(s0 + 2*sp + 1) * DHEAD + d0 + 4);
            #pragma unroll
            for (int i = 0; i < 8; i++) {
                __nv_bfloat16 h0, l0, h1, l1;
                split_bf16(v0[i], h0, l0);
                split_bf16(v1[i], h1, l1);
                VTH[(d0 + i) * 33 + sp] = pack2(h0, h1);
                VTL[(d0 + i) * 33 + sp] = pack2(l0, l1);
            }
        }
        __syncthreads();

        // ---- S = Q @ K^T  (bf16x3) ----
        float sacc[2][2][4];
        #pragma unroll
        for (int mt = 0; mt < 2; mt++)
            #pragma unroll
            for (int nt = 0; nt < 2; nt++)
                #pragma unroll
                for (int r = 0; r < 4; r++) sacc[mt][nt][r] = 0.f;

        #pragma unroll
        for (int ks = 0; ks < 8; ks++) {
            const int j0 = ks * 8;
            uint32_t bhf[2][2], blf[2][2];
            #pragma unroll
            for (int nt = 0; nt < 2; nt++) {
                const int c = wc * 16 + nt * 8 + gp;
                bhf[nt][0] = KH[c * 68 + j0 + q];
                bhf[nt][1] = KH[c * 68 + j0 + 4 + q];
                blf[nt][0] = KL[c * 68 + j0 + q];
                blf[nt][1] = KL[c * 68 + j0 + 4 + q];
            }
            #pragma unroll
            for (int mt = 0; mt < 2; mt++) {
                const int r = wr * 32 + mt * 16;
                uint32_t ah[4], al[4];
                ah[0] = QH[(r + gp) * 68 + j0 + q];
                ah[1] = QH[(r + gp + 8) * 68 + j0 + q];
                ah[2] = QH[(r + gp) * 68 + j0 + 4 + q];
                ah[3] = QH[(r + gp + 8) * 68 + j0 + 4 + q];
                al[0] = QL[(r + gp) * 68 + j0 + q];
                al[1] = QL[(r + gp + 8) * 68 + j0 + q];
                al[2] = QL[(r + gp) * 68 + j0 + 4 + q];
                al[3] = QL[(r + gp + 8) * 68 + j0 + 4 + q];
                #pragma unroll
                for (int nt = 0; nt < 2; nt++) {
                    mma_bf16(sacc[mt][nt], ah, bhf[nt]);
                    mma_bf16(sacc[mt][nt], ah, blf[nt]);
                    mma_bf16(sacc[mt][nt], al, bhf[nt]);
                }
            }
        }

        // ---- scale + causal mask + stage to SF ----
        const bool maskt = (kt >= ntiles - 2);
        #pragma unroll
        for (int mt = 0; mt < 2; mt++) {
            const int r = wr * 32 + mt * 16 + gp;
            const int qp0 = HIST + q0 + r, qp1 = qp0 + 8;
            #pragma unroll
            for (int nt = 0; nt < 2; nt++) {
                const int cc = wc * 16 + nt * 8 + 2 * q;
                float v0 = sacc[mt][nt][0] * ATT_SCALE;
                float v1 = sacc[mt][nt][1] * ATT_SCALE;
                float v2 = sacc[mt][nt][2] * ATT_SCALE;
                float v3 = sacc[mt][nt][3] * ATT_SCALE;
                if (maskt) {
                    const int s_abs = s0 + cc;
                    if (s_abs     > qp0) v0 = -1e30f;
                    if (s_abs + 1 > qp0) v1 = -1e30f;
                    if (s_abs     > qp1) v2 = -1e30f;
                    if (s_abs + 1 > qp1) v3 = -1e30f;
                }
                SF[r * 68 + cc] = v0;       SF[r * 68 + cc + 1] = v1;
                SF[(r + 8) * 68 + cc] = v2; SF[(r + 8) * 68 + cc + 1] = v3;
            }
        }
        __syncthreads();

        // ---- online softmax (4 threads/row), write P as bf16 hi/lo ----
        {
            const int row = tid >> 2, q2 = tid & 3;
            const float* prow = SF + row * 68 + q2 * 16;
            float pv[16];
            float mx = -1e30f;
            #pragma unroll
            for (int k = 0; k < 16; k++) { pv[k] = prow[k]; mx = fmaxf(mx, pv[k]); }
            mx = fmaxf(mx, __shfl_xor_sync(0xffffffffu, mx, 1));
            mx = fmaxf(mx, __shfl_xor_sync(0xffffffffu, mx, 2));
            const float m_old = m_s[row];
            const float m_new = fmaxf(m_old, mx);
            float ssum = 0.f;
            #pragma unroll
            for (int k = 0; k < 16; k++) {
                pv[k] = fast_exp(pv[k] - m_new);
                ssum += pv[k];
            }
            #pragma unroll
            for (int u = 0; u < 8; u++) {
                __nv_bfloat16 h0, l0, h1, l1;
                split_bf16(pv[2*u],   h0, l0);
                split_bf16(pv[2*u+1], h1, l1);
                PH[row * 36 + q2 * 8 + u] = pack2(h0, h1);
                PL[row * 36 + q2 * 8 + u] = pack2(l0, l1);
            }
            ssum += __shfl_xor_sync(0xffffffffu, ssum, 1);
            ssum += __shfl_xor_sync(0xffffffffu, ssum, 2);
            if (q2 == 0) {
                const float corr = fast_exp(m_old - m_new);
                l_s[row] = l_s[row] * corr + ssum;
                m_s[row] = m_new;
                c_s[row] = corr;
            }
        }
        __syncthreads();

        // ---- O = O*corr + P @ V  (bf16x3) ----
        {
            const float c0 = c_s[wor * 16 + gp];
            const float c1 = c_s[wor * 16 + gp + 8];
            #pragma unroll
            for (int nt = 0; nt < 8; nt++) {
                oacc[nt][0] *= c0; oacc[nt][1] *= c0;
                oacc[nt][2] *= c1; oacc[nt][3] *= c1;
            }
        }
        #pragma unroll
        for (int ks = 0; ks < 4; ks++) {
            const int j0 = ks * 8;
            const int r = wor * 16;
            uint32_t ph[4], pl[4];
            ph[0] = PH[(r + gp) * 36 + j0 + q];
            ph[1] = PH[(r + gp + 8) * 36 + j0 + q];
            ph[2] = PH[(r + gp) * 36 + j0 + 4 + q];
            ph[3] = PH[(r + gp + 8) * 36 + j0 + 4 + q];
            pl[0] = PL[(r + gp) * 36 + j0 + q];
            pl[1] = PL[(r + gp + 8) * 36 + j0 + q];
            pl[2] = PL[(r + gp) * 36 + j0 + 4 + q];
            pl[3] = PL[(r + gp + 8) * 36 + j0 + 4 + q];
            #pragma unroll
            for (int nt = 0; nt < 8; nt++) {
                const int c = woc * 64 + nt * 8 + gp;
                uint32_t bvh[2], bvl[2];
                bvh[0] = VTH[c * 33 + j0 + q];
                bvh[1] = VTH[c * 33 + j0 + 4 + q];
                bvl[0] = VTL[c * 33 + j0 + q];
                bvl[1] = VTL[c * 33 + j0 + 4 + q];
                mma_bf16(oacc[nt], ph, bvh);
                mma_bf16(oacc[nt], ph, bvl);
                mma_bf16(oacc[nt], pl, bvh);
            }
        }
        __syncthreads();
    }

    // ---- epilogue ----
    {
        const int r = wor * 16 + gp;
        const float inv0 = 1.f / l_s[r];
        const float inv1 = 1.f / l_s[r + 8];
        const int t0 = b * SQ + q0 + r;
        #pragma unroll
        for (int nt = 0; nt < 8; nt++) {
            const int c = woc * 64 + nt * 8 + 2 * q;
            float2 w0, w1;
            w0.x = oacc[nt][0] * inv0; w0.y = oacc[nt][1] * inv0;
            w1.x = oacc[nt][2] * inv1; w1.y = oacc[nt][3] * inv1;
            *(float2*)&Og[(size_t)t0 * D_MODEL + h * DHEAD + c]       = w0;
            *(float2*)&Og[(size_t)(t0 + 8) * D_MODEL + h * DHEAD + c] = w1;
        }
    }
}

// =====================================================================
// launch
// =====================================================================
extern "C" void kernel_launch(void* const* d_in, const int* in_sizes, int n_in,
                              void* d_out, int out_size)
{
    const float* hidden  = (const float*)d_in[0];
    const float* w_qkv   = (const float*)d_in[1];
    const float* b_qkv   = (const float*)d_in[2];
    const float* w_proj  = (const float*)d_in[3];
    const float* cosT    = (const float*)d_in[4];
    const float* sinT    = (const float*)d_in[5];
    const float* kcache  = (const float*)d_in[6];
    const float* vcache  = (const float*)d_in[7];
    const int*   blkOff  = (const int*)d_in[8];
    float* out = (float*)d_out;

    float *qkv_p, *k_p, *v_p, *attn_p;
    cudaGetSymbolAddress((void**)&qkv_p,  g_qkv);
    cudaGetSymbolAddress((void**)&k_p,    g_k);
    cudaGetSymbolAddress((void**)&v_p,    g_v);
    cudaGetSymbolAddress((void**)&attn_p, g_attn);

    cudaFuncSetAttribute(tf32_gemm_kernel,
                         cudaFuncAttributeMaxDynamicSharedMemorySize, G_SMEM_BYTES);
    cudaFuncSetAttribute(flash_v2_kernel,
                         cudaFuncAttributeMaxDynamicSharedMemorySize, FL_SMEM_BYTES);

    // 1) QKV projection (tf32, double-buffered)
    tf32_gemm_kernel<<<dim3(3 * D_MODEL / 128, T_TOK / 128), 256, G_SMEM_BYTES>>>(
        hidden, w_qkv, b_qkv, qkv_p, T_TOK, 3 * D_MODEL, D_MODEL);

    // 2) build contiguous K/V (cache gather + RoPE on new K)
    build_kv_kernel<<<dim3(SKV, B_SEQ), 128>>>(
        qkv_p, kcache, vcache, blkOff, cosT, sinT, k_p, v_p);

    // 3) causal flash attention (RoPE+logn on Q fused; bf16x3 numerics)
    flash_v2_kernel<<<dim3(B_SEQ * H_HEADS, SQ / 128), 512, FL_SMEM_BYTES>>>(
        qkv_p, k_p, v_p, cosT, sinT, attn_p);

    // 4) output projection (tf32, double-buffered)
    tf32_gemm_kernel<<<dim3(D_MODEL / 128, T_TOK / 128), 256, G_SMEM_BYTES>>>(
        attn_p, w_proj, nullptr, out, T_TOK, D_MODEL, D_MODEL);
}

// round 7
// speedup vs baseline: 1.1900x; 1.0004x over previous
#include <cuda_runtime.h>
#include <cuda_bf16.h>
#include <cstdint>

// ---------------- problem geometry ----------------
#define T_TOK   4096
#define D_MODEL 4096
#define H_HEADS 32
#define DHEAD   128
#define B_SEQ   4
#define SQ      1024
#define HIST    1024
#define SKV     2048
#define NBLK    32
#define BS_PAGE 64
#define ATT_SCALE  0.08838834764831845f
#define INV_LN1024 0.14426950408889634f

// ---------------- scratch ----------------
__device__ float g_qkv[50331648];   // [T, 3*D]
__device__ float g_k  [33554432];   // [B,H,SKV,DH]
__device__ float g_v  [33554432];   // [B,H,SKV,DH]
__device__ float g_attn[16777216];  // [T, D]

// ---------------- helpers ----------------
__device__ __forceinline__ uint32_t f2tf32(float f) {
    uint32_t u;
    asm("cvt.rna.tf32.f32 %0, %1;" : "=r"(u) : "f"(f));
    return u;
}
__device__ __forceinline__ uint32_t pack2(__nv_bfloat16 a, __nv_bfloat16 b) {
    __nv_bfloat162 t = __nv_bfloat162(a, b);   // a -> low 16 bits (k even)
    return *reinterpret_cast<uint32_t*>(&t);
}
__device__ __forceinline__ void split_bf16(float f, __nv_bfloat16& h, __nv_bfloat16& l) {
    h = __float2bfloat16(f);
    l = __float2bfloat16(f - __bfloat162float(h));
}
__device__ __forceinline__ void mma_bf16(float* c, const uint32_t* a, const uint32_t* b) {
    asm volatile(
        "mma.sync.aligned.m16n8k16.row.col.f32.bf16.bf16.f32 "
        "{%0,%1,%2,%3}, {%4,%5,%6,%7}, {%8,%9}, {%0,%1,%2,%3};"
        : "+f"(c[0]), "+f"(c[1]), "+f"(c[2]), "+f"(c[3])
        : "r"(a[0]), "r"(a[1]), "r"(a[2]), "r"(a[3]), "r"(b[0]), "r"(b[1]));
}
__device__ __forceinline__ void mma_tf32(float* c, const uint32_t* a, const uint32_t* b) {
    asm volatile(
        "mma.sync.aligned.m16n8k8.row.col.f32.tf32.tf32.f32 "
        "{%0,%1,%2,%3}, {%4,%5,%6,%7}, {%8,%9}, {%0,%1,%2,%3};"
        : "+f"(c[0]), "+f"(c[1]), "+f"(c[2]), "+f"(c[3])
        : "r"(a[0]), "r"(a[1]), "r"(a[2]), "r"(a[3]), "r"(b[0]), "r"(b[1]));
}
// exp(x) for x <= 0, FMA-pipe only. ~1e-7 rel err.
__device__ __forceinline__ float fast_exp(float x) {
    float y = fmaxf(x * 1.4426950408889634f, -126.f);
    float z = __fadd_rn(y, 12582912.f);
    int   n = __float_as_int(z) - 0x4B400000;
    float f = y - __fsub_rn(z, 12582912.f);
    float t = f * 0.6931471805599453f;
    float p = __fmaf_rn(t, 0.0013888889f, 0.0083333333f);
    p = __fmaf_rn(t, p, 0.0416666667f);
    p = __fmaf_rn(t, p, 0.1666666667f);
    p = __fmaf_rn(t, p, 0.5f);
    p = __fmaf_rn(t, p, 1.0f);
    p = __fmaf_rn(t, p, 1.0f);
    return p * __int_as_float((n + 127) << 23);
}

// =====================================================================
// TF32 GEMM, double-buffered: C[M,N] = A[M,K] @ B[K,N] (+bias)
// 128x128x32 tile, 8 warps (2x4), warp tile 64x32, m16n8k8 tf32.
// smem (u32): As[2][128][36], Bs[2][32][136]  = 71680 B
// =====================================================================
#define G_SMEM_BYTES (17920 * 4)

__global__ __launch_bounds__(256, 2) void tf32_gemm_kernel(
    const float* __restrict__ A, const float* __restrict__ Bm,
    const float* __restrict__ bias, float* __restrict__ C,
    int M, int N, int K)
{
    extern __shared__ uint32_t sg[];
    uint32_t* AsB[2] = { sg,        sg + 4608 };
    uint32_t* BsB[2] = { sg + 9216, sg + 13568 };

    const int tid  = threadIdx.x;
    const int brow = blockIdx.y, bcol = blockIdx.x;
    const int warp = tid >> 5, lane = tid & 31;
    const int wr = warp >> 2, wc = warp & 3;
    const int gp = lane >> 2, q = lane & 3;

    float acc[4][4][4];
    #pragma unroll
    for (int mt = 0; mt < 4; mt++)
        #pragma unroll
        for (int nt = 0; nt < 4; nt++)
            #pragma unroll
            for (int r = 0; r < 4; r++) acc[mt][nt][r] = 0.f;

    const float* Ab = A + (size_t)(brow * 128) * K;
    const float* Bb = Bm + (size_t)bcol * 128;

    float4 av[4], bv[4];
    auto load_regs = [&](int kt) {
        #pragma unroll
        for (int i = 0; i < 4; i++) {
            const int u = tid + 256 * i;
            av[i] = *(const float4*)(Ab + (size_t)(u >> 3) * K + kt + ((u & 7) << 2));
            bv[i] = *(const float4*)(Bb + (size_t)(kt + (u >> 5)) * N + ((u & 31) << 2));
        }
    };
    auto store_stage = [&](int st) {
        uint32_t* As = AsB[st];
        uint32_t* Bs = BsB[st];
        #pragma unroll
        for (int i = 0; i < 4; i++) {
            const int u = tid + 256 * i;
            uint4 ta, tb;
            ta.x = f2tf32(av[i].x); ta.y = f2tf32(av[i].y);
            ta.z = f2tf32(av[i].z); ta.w = f2tf32(av[i].w);
            tb.x = f2tf32(bv[i].x); tb.y = f2tf32(bv[i].y);
            tb.z = f2tf32(bv[i].z); tb.w = f2tf32(bv[i].w);
            *(uint4*)&As[(u >> 3) * 36 + ((u & 7) << 2)]   = ta;
            *(uint4*)&Bs[(u >> 5) * 136 + ((u & 31) << 2)] = tb;
        }
    };

    load_regs(0);
    store_stage(0);
    __syncthreads();

    for (int kt = 0; kt < K; kt += 32) {
        const int buf = (kt >> 5) & 1;
        const bool more = (kt + 32 < K);
        if (more) load_regs(kt + 32);

        const uint32_t* As = AsB[buf];
        const uint32_t* Bs = BsB[buf];
        #pragma unroll
        for (int kk = 0; kk < 32; kk += 8) {
            uint32_t af[4][4], bf[4][2];
            #pragma unroll
            for (int mt = 0; mt < 4; mt++) {
                const int r = wr * 64 + mt * 16 + gp;
                af[mt][0] = As[r * 36 + kk + q];
                af[mt][1] = As[(r + 8) * 36 + kk + q];
                af[mt][2] = As[r * 36 + kk + q + 4];
                af[mt][3] = As[(r + 8) * 36 + kk + q + 4];
            }
            #pragma unroll
            for (int nt = 0; nt < 4; nt++) {
                const int c = wc * 32 + nt * 8 + gp;
                bf[nt][0] = Bs[(kk + q) * 136 + c];
                bf[nt][1] = Bs[(kk + q + 4) * 136 + c];
            }
            #pragma unroll
            for (int mt = 0; mt < 4; mt++)
                #pragma unroll
                for (int nt = 0; nt < 4; nt++)
                    mma_tf32(acc[mt][nt], af[mt], bf[nt]);
        }
        if (more) store_stage(buf ^ 1);
        __syncthreads();
    }

    #pragma unroll
    for (int mt = 0; mt < 4; mt++) {
        const int r0 = brow * 128 + wr * 64 + mt * 16 + gp;
        #pragma unroll
        for (int nt = 0; nt < 4; nt++) {
            const int c0 = bcol * 128 + wc * 32 + nt * 8 + 2 * q;
            float bb0 = 0.f, bb1 = 0.f;
            if (bias) { bb0 = bias[c0]; bb1 = bias[c0 + 1]; }
            float2 v0, v1;
            v0.x = acc[mt][nt][0] + bb0; v0.y = acc[mt][nt][1] + bb1;
            v1.x = acc[mt][nt][2] + bb0; v1.y = acc[mt][nt][3] + bb1;
            *(float2*)&C[(size_t)r0 * N + c0]       = v0;
            *(float2*)&C[(size_t)(r0 + 8) * N + c0] = v1;
        }
    }
}

// =====================================================================
// Build contiguous K/V [B,H,SKV,DH].
// =====================================================================
__global__ void build_kv_kernel(const float* __restrict__ qkv,
                                const float* __restrict__ kcache,
                                const float* __restrict__ vcache,
                                const int* __restrict__ blockOff,
                                const float* __restrict__ cosT,
                                const float* __restrict__ sinT,
                                float* __restrict__ Kout,
                                float* __restrict__ Vout)
{
    const int s = blockIdx.x, b = blockIdx.y, d = threadIdx.x;
    if (s < HIST) {
        const int blk = blockOff[b * NBLK + (s >> 6)];
        const size_t src = ((size_t)(blk * BS_PAGE + (s & 63))) * H_HEADS * DHEAD;
        for (int h = 0; h < H_HEADS; h++) {
            const size_t dst = (((size_t)(b * H_HEADS + h)) * SKV + s) * DHEAD + d;
            Kout[dst] = kcache[src + h * DHEAD + d];
            Vout[dst] = vcache[src + h * DHEAD + d];
        }
    } else {
        const int t = b * SQ + (s - HIST);
        const int pos = s;
        const float c  = cosT[(size_t)pos * DHEAD + d];
        const float sn = sinT[(size_t)pos * DHEAD + d];
        const float* kp = qkv + (size_t)t * (3 * D_MODEL) + D_MODEL;
        const float* vp = kp + D_MODEL;
        for (int h = 0; h < H_HEADS; h++) {
            const float k1 = kp[h * DHEAD + d];
            const float rot = (d < 64) ? -kp[h * DHEAD + d + 64]
                                       :  kp[h * DHEAD + d - 64];
            const size_t dst = (((size_t)(b * H_HEADS + h)) * SKV + s) * DHEAD + d;
            Kout[dst] = k1 * c + rot * sn;
            Vout[dst] = vp[h * DHEAD + d];
        }
    }
}

// =====================================================================
// Flash attention v2, bf16x3 numerics on mma.sync tensor cores.
// CTA: 512 threads, q-tile 128, fused RoPE+logn on Q load.
// smem layout (u32 offsets):
//   QH 0        [128][68]     QL 8704
//   KH 17408    [64][68]      KL 21760
//   VTH 26112   [128][33]     VTL 30336   (V transposed: [d][s-pair])
//   SF 34560    [128][68] f32
//   PH 43264    [128][36]     PL 47872
//   STATS 52480 (m 128, l 128, c 128)
// total 52864 u32 = 211456 B
// =====================================================================
#define FL_QH   0
#define FL_QL   8704
#define FL_KH   17408
#define FL_KL   21760
#define FL_VTH  26112
#define FL_VTL  30336
#define FL_SF   34560
#define FL_PH   43264
#define FL_PL   47872
#define FL_ST   52480
#define FL_SMEM_BYTES (52864 * 4)

__global__ __launch_bounds__(512) void flash_v2_kernel(
    const float* __restrict__ Qg,   // g_qkv (raw q section; RoPE applied here)
    const float* __restrict__ Kg,
    const float* __restrict__ Vg,
    const float* __restrict__ cosT,
    const float* __restrict__ sinT,
    float* __restrict__ Og)
{
    extern __shared__ uint32_t fsm[];
    uint32_t* QH  = fsm + FL_QH;
    uint32_t* QL  = fsm + FL_QL;
    uint32_t* KH  = fsm + FL_KH;
    uint32_t* KL  = fsm + FL_KL;
    uint32_t* VTH = fsm + FL_VTH;
    uint32_t* VTL = fsm + FL_VTL;
    float*    SF  = (float*)(fsm + FL_SF);
    uint32_t* PH  = fsm + FL_PH;
    uint32_t* PL  = fsm + FL_PL;
    float* m_s = (float*)(fsm + FL_ST);
    float* l_s = m_s + 128;
    float* c_s = l_s + 128;

    const int bh = blockIdx.x;
    const int b = bh >> 5, h = bh & 31;
    const int q0 = blockIdx.y * 128;
    const int tid = threadIdx.x;
    const int warp = tid >> 5, lane = tid & 31;
    const int gp = lane >> 2, q = lane & 3;
    const int wr = warp >> 2, wc = warp & 3;     // S phase: 4x4 warps
    const int wor = warp >> 1, woc = warp & 1;   // PV phase: 8x2 warps

    // ---- load Q tile + RoPE + logn + bf16 split ----
    {
        const int row = tid >> 2;
        const int d0  = (tid & 3) * 16;
        const int t   = b * SQ + q0 + row;
        const int pos = HIST + q0 + row;
        const float logn = logf((float)(pos + 1)) * INV_LN1024;
        const float* qrow = Qg + (size_t)t * (3 * D_MODEL) + h * DHEAD;
        const float* crow = cosT + (size_t)pos * DHEAD;
        const float* srow = sinT + (size_t)pos * DHEAD;
        float qa[16], qb[16], ca[16], cb[16], sa[16], sb[16];
        #pragma unroll
        for (int i = 0; i < 4; i++) {
            *(float4*)&qa[4*i] = *(const float4*)(qrow + d0 + 4*i);
            *(float4*)&qb[4*i] = *(const float4*)(qrow + d0 + 64 + 4*i);
            *(float4*)&ca[4*i] = *(const float4*)(crow + d0 + 4*i);
            *(float4*)&cb[4*i] = *(const float4*)(crow + d0 + 64 + 4*i);
            *(float4*)&sa[4*i] = *(const float4*)(srow + d0 + 4*i);
            *(float4*)&sb[4*i] = *(const float4*)(srow + d0 + 64 + 4*i);
        }
        #pragma unroll
        for (int j = 0; j < 8; j++) {       // pairs within each 16-wide range
            float f0 = (qa[2*j]   * ca[2*j]   - qb[2*j]   * sa[2*j])   * logn;
            float f1 = (qa[2*j+1] * ca[2*j+1] - qb[2*j+1] * sa[2*j+1]) * logn;
            float g0 = (qb[2*j]   * cb[2*j]   + qa[2*j]   * sb[2*j])   * logn;
            float g1 = (qb[2*j+1] * cb[2*j+1] + qa[2*j+1] * sb[2*j+1]) * logn;
            __nv_bfloat16 h0, l0, h1, l1;
            split_bf16(f0, h0, l0); split_bf16(f1, h1, l1);
            QH[row * 68 + d0/2 + j] = pack2(h0, h1);
            QL[row * 68 + d0/2 + j] = pack2(l0, l1);
            split_bf16(g0, h0, l0); split_bf16(g1, h1, l1);
            QH[row * 68 + (d0 + 64)/2 + j] = pack2(h0, h1);
            QL[row * 68 + (d0 + 64)/2 + j] = pack2(l0, l1);
        }
    }
    if (tid < 128) { m_s[tid] = -1e30f; l_s[tid] = 0.f; }

    float oacc[8][4];
    #pragma unroll
    for (int nt = 0; nt < 8; nt++)
        { oacc[nt][0]=0.f; oacc[nt][1]=0.f; oacc[nt][2]=0.f; oacc[nt][3]=0.f; }

    const float* Kbh = Kg + (size_t)bh * SKV * DHEAD;
    const float* Vbh = Vg + (size_t)bh * SKV * DHEAD;
    const int ntiles = (HIST + q0 + 128) / 64;
    __syncthreads();

    for (int kt = 0; kt < ntiles; kt++) {
        const int s0 = kt * 64;
        // ---- load K tile (bf16 split, [s][d-pair]) ----
        {
            const int s  = tid >> 3;
            const int d0 = (tid & 7) * 16;
            float kf[16];
            #pragma unroll
            for (int i = 0; i < 4; i++)
                *(float4*)&kf[4*i] = *(const float4*)(Kbh + (size_t)(s0 + s) * DHEAD + d0 + 4*i);
            #pragma unroll
            for (int j = 0; j < 8; j++) {
                __nv_bfloat16 h0, l0, h1, l1;
                split_bf16(kf[2*j],   h0, l0);
                split_bf16(kf[2*j+1], h1, l1);
                KH[s * 68 + d0/2 + j] = pack2(h0, h1);
                KL[s * 68 + d0/2 + j] = pack2(l0, l1);
            }
        }
        // ---- load V tile transposed (bf16 split, [d][s-pair]) ----
        {
            const int sp = tid >> 4;            // 0..31 s-pairs
            const int d0 = (tid & 15) * 8;
            float v0[8], v1[8];
            *(float4*)&v0[0] = *(const float4*)(Vbh + (size_t)(s0 + 2*sp)     * DHEAD + d0);
            *(float4*)&v0[4] = *(const float4*)(Vbh + (size_t)(s0 + 2*sp)     * DHEAD + d0 + 4);
            *(float4*)&v1[0] = *(const float4*)(Vbh + (size_t)(s0 + 2*sp + 1) * DHEAD + d0);
            *(float4*)&v1[4] = *(const float4*)(Vbh + (size_t)(s0 + 2*sp + 1) * DHEAD + d0 + 4);
            #pragma unroll
            for (int i = 0; i < 8; i++) {
                __nv_bfloat16 h0, l0, h1, l1;
                split_bf16(v0[i], h0, l0);
                split_bf16(v1[i], h1, l1);
                VTH[(d0 + i) * 33 + sp] = pack2(h0, h1);
                VTL[(d0 + i) * 33 + sp] = pack2(l0, l1);
            }
        }
        __syncthreads();

        // ---- S = Q @ K^T  (bf16x3) ----
        float sacc[2][2][4];
        #pragma unroll
        for (int mt = 0; mt < 2; mt++)
            #pragma unroll
            for (int nt = 0; nt < 2; nt++)
                #pragma unroll
                for (int r = 0; r < 4; r++) sacc[mt][nt][r] = 0.f;

        #pragma unroll
        for (int ks = 0; ks < 8; ks++) {
            const int j0 = ks * 8;
            uint32_t bhf[2][2], blf[2][2];
            #pragma unroll
            for (int nt = 0; nt < 2; nt++) {
                const int c = wc * 16 + nt * 8 + gp;
                bhf[nt][0] = KH[c * 68 + j0 + q];
                bhf[nt][1] = KH[c * 68 + j0 + 4 + q];
                blf[nt][0] = KL[c * 68 + j0 + q];
                blf[nt][1] = KL[c * 68 + j0 + 4 + q];
            }
            #pragma unroll
            for (int mt = 0; mt < 2; mt++) {
                const int r = wr * 32 + mt * 16;
                uint32_t ah[4], al[4];
                ah[0] = QH[(r + gp) * 68 + j0 + q];
                ah[1] = QH[(r + gp + 8) * 68 + j0 + q];
                ah[2] = QH[(r + gp) * 68 + j0 + 4 + q];
                ah[3] = QH[(r + gp + 8) * 68 + j0 + 4 + q];
                al[0] = QL[(r + gp) * 68 + j0 + q];
                al[1] = QL[(r + gp + 8) * 68 + j0 + q];
                al[2] = QL[(r + gp) * 68 + j0 + 4 + q];
                al[3] = QL[(r + gp + 8) * 68 + j0 + 4 + q];
                #pragma unroll
                for (int nt = 0; nt < 2; nt++) {
                    mma_bf16(sacc[mt][nt], ah, bhf[nt]);
                    mma_bf16(sacc[mt][nt], ah, blf[nt]);
                    mma_bf16(sacc[mt][nt], al, bhf[nt]);
                }
            }
        }

        // ---- scale + causal mask + stage to SF ----
        const bool maskt = (kt >= ntiles - 2);
        #pragma unroll
        for (int mt = 0; mt < 2; mt++) {
            const int r = wr * 32 + mt * 16 + gp;
            const int qp0 = HIST + q0 + r, qp1 = qp0 + 8;
            #pragma unroll
            for (int nt = 0; nt < 2; nt++) {
                const int cc = wc * 16 + nt * 8 + 2 * q;
                float v0 = sacc[mt][nt][0] * ATT_SCALE;
                float v1 = sacc[mt][nt][1] * ATT_SCALE;
                float v2 = sacc[mt][nt][2] * ATT_SCALE;
                float v3 = sacc[mt][nt][3] * ATT_SCALE;
                if (maskt) {
                    const int s_abs = s0 + cc;
                    if (s_abs     > qp0) v0 = -1e30f;
                    if (s_abs + 1 > qp0) v1 = -1e30f;
                    if (s_abs     > qp1) v2 = -1e30f;
                    if (s_abs + 1 > qp1) v3 = -1e30f;
                }
                SF[r * 68 + cc] = v0;       SF[r * 68 + cc + 1] = v1;
                SF[(r + 8) * 68 + cc] = v2; SF[(r + 8) * 68 + cc + 1] = v3;
            }
        }
        __syncthreads();

        // ---- online softmax (4 threads/row), write P as bf16 hi/lo ----
        {
            const int row = tid >> 2, q2 = tid & 3;
            const float* prow = SF + row * 68 + q2 * 16;
            float pv[16];
            float mx = -1e30f;
            #pragma unroll
            for (int k = 0; k < 16; k++) { pv[k] = prow[k]; mx = fmaxf(mx, pv[k]); }
            mx = fmaxf(mx, __shfl_xor_sync(0xffffffffu, mx, 1));
            mx = fmaxf(mx, __shfl_xor_sync(0xffffffffu, mx, 2));
            const float m_old = m_s[row];
            const float m_new = fmaxf(m_old, mx);
            float ssum = 0.f;
            #pragma unroll
            for (int k = 0; k < 16; k++) {
                pv[k] = fast_exp(pv[k] - m_new);
                ssum += pv[k];
            }
            #pragma unroll
            for (int u = 0; u < 8; u++) {
                __nv_bfloat16 h0, l0, h1, l1;
                split_bf16(pv[2*u],   h0, l0);
                split_bf16(pv[2*u+1], h1, l1);
                PH[row * 36 + q2 * 8 + u] = pack2(h0, h1);
                PL[row * 36 + q2 * 8 + u] = pack2(l0, l1);
            }
            ssum += __shfl_xor_sync(0xffffffffu, ssum, 1);
            ssum += __shfl_xor_sync(0xffffffffu, ssum, 2);
            if (q2 == 0) {
                const float corr = fast_exp(m_old - m_new);
                l_s[row] = l_s[row] * corr + ssum;
                m_s[row] = m_new;
                c_s[row] = corr;
            }
        }
        __syncthreads();

        // ---- O = O*corr + P @ V  (bf16x3) ----
        {
            const float c0 = c_s[wor * 16 + gp];
            const float c1 = c_s[wor * 16 + gp + 8];
            #pragma unroll
            for (int nt = 0; nt < 8; nt++) {
                oacc[nt][0] *= c0; oacc[nt][1] *= c0;
                oacc[nt][2] *= c1; oacc[nt][3] *= c1;
            }
        }
        #pragma unroll
        for (int ks = 0; ks < 4; ks++) {
            const int j0 = ks * 8;
            const int r = wor * 16;
            uint32_t ph[4], pl[4];
            ph[0] = PH[(r + gp) * 36 + j0 + q];
            ph[1] = PH[(r + gp + 8) * 36 + j0 + q];
            ph[2] = PH[(r + gp) * 36 + j0 + 4 + q];
            ph[3] = PH[(r + gp + 8) * 36 + j0 + 4 + q];
            pl[0] = PL[(r + gp) * 36 + j0 + q];
            pl[1] = PL[(r + gp + 8) * 36 + j0 + q];
            pl[2] = PL[(r + gp) * 36 + j0 + 4 + q];
            pl[3] = PL[(r + gp + 8) * 36 + j0 + 4 + q];
            #pragma unroll
            for (int nt = 0; nt < 8; nt++) {
                const int c = woc * 64 + nt * 8 + gp;
                uint32_t bvh[2], bvl[2];
                bvh[0] = VTH[c * 33 + j0 + q];
                bvh[1] = VTH[c * 33 + j0 + 4 + q];
                bvl[0] = VTL[c * 33 + j0 + q];
                bvl[1] = VTL[c * 33 + j0 + 4 + q];
                mma_bf16(oacc[nt], ph, bvh);
                mma_bf16(oacc[nt], ph, bvl);
                mma_bf16(oacc[nt], pl, bvh);
            }
        }
        __syncthreads();
    }

    // ---- epilogue ----
    {
        const int r = wor * 16 + gp;
        const float inv0 = 1.f / l_s[r];
        const float inv1 = 1.f / l_s[r + 8];
        const int t0 = b * SQ + q0 + r;
        #pragma unroll
        for (int nt = 0; nt < 8; nt++) {
            const int c = woc * 64 + nt * 8 + 2 * q;
            float2 w0, w1;
            w0.x = oacc[nt][0] * inv0; w0.y = oacc[nt][1] * inv0;
            w1.x = oacc[nt][2] * inv1; w1.y = oacc[nt][3] * inv1;
            *(float2*)&Og[(size_t)t0 * D_MODEL + h * DHEAD + c]       = w0;
            *(float2*)&Og[(size_t)(t0 + 8) * D_MODEL + h * DHEAD + c] = w1;
        }
    }
}

// =====================================================================
// launch
// =====================================================================
extern "C" void kernel_launch(void* const* d_in, const int* in_sizes, int n_in,
                              void* d_out, int out_size)
{
    const float* hidden  = (const float*)d_in[0];
    const float* w_qkv   = (const float*)d_in[1];
    const float* b_qkv   = (const float*)d_in[2];
    const float* w_proj  = (const float*)d_in[3];
    const float* cosT    = (const float*)d_in[4];
    const float* sinT    = (const float*)d_in[5];
    const float* kcache  = (const float*)d_in[6];
    const float* vcache  = (const float*)d_in[7];
    const int*   blkOff  = (const int*)d_in[8];
    float* out = (float*)d_out;

    float *qkv_p, *k_p, *v_p, *attn_p;
    cudaGetSymbolAddress((void**)&qkv_p,  g_qkv);
    cudaGetSymbolAddress((void**)&k_p,    g_k);
    cudaGetSymbolAddress((void**)&v_p,    g_v);
    cudaGetSymbolAddress((void**)&attn_p, g_attn);

    cudaFuncSetAttribute(tf32_gemm_kernel,
                         cudaFuncAttributeMaxDynamicSharedMemorySize, G_SMEM_BYTES);
    cudaFuncSetAttribute(flash_v2_kernel,
                         cudaFuncAttributeMaxDynamicSharedMemorySize, FL_SMEM_BYTES);

    // 1) QKV projection (tf32, double-buffered)
    tf32_gemm_kernel<<<dim3(3 * D_MODEL / 128, T_TOK / 128), 256, G_SMEM_BYTES>>>(
        hidden, w_qkv, b_qkv, qkv_p, T_TOK, 3 * D_MODEL, D_MODEL);

    // 2) build contiguous K/V (cache gather + RoPE on new K)
    build_kv_kernel<<<dim3(SKV, B_SEQ), 128>>>(
        qkv_p, kcache, vcache, blkOff, cosT, sinT, k_p, v_p);

    // 3) causal flash attention (RoPE+logn on Q fused; bf16x3 numerics)
    flash_v2_kernel<<<dim3(B_SEQ * H_HEADS, SQ / 128), 512, FL_SMEM_BYTES>>>(
        qkv_p, k_p, v_p, cosT, sinT, attn_p);

    // 4) output projection (tf32, double-buffered)
    tf32_gemm_kernel<<<dim3(D_MODEL / 128, T_TOK / 128), 256, G_SMEM_BYTES>>>(
        attn_p, w_proj, nullptr, out, T_TOK, D_MODEL, D_MODEL);
}

// round 8
// speedup vs baseline: 1.5461x; 1.2992x over previous
#include <cuda_runtime.h>
#include <cuda_bf16.h>
#include <cstdint>

// ---------------- problem geometry ----------------
#define T_TOK   4096
#define D_MODEL 4096
#define H_HEADS 32
#define DHEAD   128
#define B_SEQ   4
#define SQ      1024
#define HIST    1024
#define SKV     2048
#define NBLK    32
#define BS_PAGE 64
#define ATT_SCALE  0.08838834764831845f
#define INV_LN1024 0.14426950408889634f

// ---------------- scratch ----------------
__device__ float g_qkv[50331648];            // [T, 3*D]
__device__ float g_attn[16777216];           // [T, D]
__device__ float g_wqkvT[50331648];          // [3D, D] tf32-rounded, transposed
__device__ float g_wprojT[16777216];         // [D, D]
__device__ __nv_bfloat16 g_kh[33554432];     // [B,H,SKV,DH] hi
__device__ __nv_bfloat16 g_kl[33554432];     // lo
__device__ __nv_bfloat16 g_vh[33554432];
__device__ __nv_bfloat16 g_vl[33554432];

// ---------------- helpers ----------------
__device__ __forceinline__ uint32_t smem_u32(const void* p) {
    uint32_t a;
    asm("{ .reg .u64 t; cvta.to.shared.u64 t, %1; cvt.u32.u64 %0, t; }"
        : "=r"(a) : "l"(p));
    return a;
}
__device__ __forceinline__ uint32_t f2tf32(float f) {
    uint32_t u;
    asm("cvt.rna.tf32.f32 %0, %1;" : "=r"(u) : "f"(f));
    return u;
}
__device__ __forceinline__ uint32_t pack2(__nv_bfloat16 a, __nv_bfloat16 b) {
    __nv_bfloat162 t = __nv_bfloat162(a, b);   // a -> low 16 bits (k even)
    return *reinterpret_cast<uint32_t*>(&t);
}
__device__ __forceinline__ void split_bf16(float f, __nv_bfloat16& h, __nv_bfloat16& l) {
    h = __float2bfloat16(f);
    l = __float2bfloat16(f - __bfloat162float(h));
}
#define LDSM_X4(R0,R1,R2,R3,A) \
    asm volatile("ldmatrix.sync.aligned.m8n8.x4.shared.b16 {%0,%1,%2,%3}, [%4];" \
                 : "=r"(R0), "=r"(R1), "=r"(R2), "=r"(R3) : "r"(A))
#define LDSM_X4_T(R0,R1,R2,R3,A) \
    asm volatile("ldmatrix.sync.aligned.m8n8.x4.trans.shared.b16 {%0,%1,%2,%3}, [%4];" \
                 : "=r"(R0), "=r"(R1), "=r"(R2), "=r"(R3) : "r"(A))
__device__ __forceinline__ void mma_bf16(float* c, const uint32_t* a, const uint32_t* b) {
    asm volatile(
        "mma.sync.aligned.m16n8k16.row.col.f32.bf16.bf16.f32 "
        "{%0,%1,%2,%3}, {%4,%5,%6,%7}, {%8,%9}, {%0,%1,%2,%3};"
        : "+f"(c[0]), "+f"(c[1]), "+f"(c[2]), "+f"(c[3])
        : "r"(a[0]), "r"(a[1]), "r"(a[2]), "r"(a[3]), "r"(b[0]), "r"(b[1]));
}
__device__ __forceinline__ void mma_tf32(float* c, const uint32_t* a, const uint32_t* b) {
    asm volatile(
        "mma.sync.aligned.m16n8k8.row.col.f32.tf32.tf32.f32 "
        "{%0,%1,%2,%3}, {%4,%5,%6,%7}, {%8,%9}, {%0,%1,%2,%3};"
        : "+f"(c[0]), "+f"(c[1]), "+f"(c[2]), "+f"(c[3])
        : "r"(a[0]), "r"(a[1]), "r"(a[2]), "r"(a[3]), "r"(b[0]), "r"(b[1]));
}
// exp(x) for x <= 0, FMA-pipe only. ~1e-7 rel err.
__device__ __forceinline__ float fast_exp(float x) {
    float y = fmaxf(x * 1.4426950408889634f, -126.f);
    float z = __fadd_rn(y, 12582912.f);
    int   n = __float_as_int(z) - 0x4B400000;
    float f = y - __fsub_rn(z, 12582912.f);
    float t = f * 0.6931471805599453f;
    float p = __fmaf_rn(t, 0.0013888889f, 0.0083333333f);
    p = __fmaf_rn(t, p, 0.0416666667f);
    p = __fmaf_rn(t, p, 0.1666666667f);
    p = __fmaf_rn(t, p, 0.5f);
    p = __fmaf_rn(t, p, 1.0f);
    p = __fmaf_rn(t, p, 1.0f);
    return p * __int_as_float((n + 127) << 23);
}

// =====================================================================
// Prep: W[K][N] fp32 -> WT[N][K] fp32 with tf32(RNA) rounding applied.
// =====================================================================
__global__ __launch_bounds__(256) void transpose_tf32_kernel(
    const float* __restrict__ W, float* __restrict__ WT, int Kd, int Nd)
{
    __shared__ float ts[32][33];
    const int n0 = blockIdx.x * 32, k0 = blockIdx.y * 32;
    const int tx = threadIdx.x, ty = threadIdx.y;
    #pragma unroll
    for (int j = ty; j < 32; j += 8)
        ts[j][tx] = W[(size_t)(k0 + j) * Nd + n0 + tx];
    __syncthreads();
    #pragma unroll
    for (int j = ty; j < 32; j += 8)
        WT[(size_t)(n0 + j) * Kd + k0 + tx] = __uint_as_float(f2tf32(ts[tx][j]));
}

// =====================================================================
// TF32 GEMM w/ ldmatrix: C[M,N] = A[M,K] @ B[K,N] (+bias)
// B passed PRE-TRANSPOSED+ROUNDED as BT[N][K].
// 128x128x32 tile, 8 warps (2x4), warp tile 64x32, m16n8k8 tf32.
// smem (u32): As[2][128][36], Bs[2][128][36]  -> 73728 B
// =====================================================================
#define G_SMEM_BYTES (18432 * 4)

__global__ __launch_bounds__(256, 2) void tf32_gemm_ldsm_kernel(
    const float* __restrict__ A, const float* __restrict__ BT,
    const float* __restrict__ bias, float* __restrict__ C,
    int M, int N, int K)
{
    extern __shared__ uint32_t sg[];
    uint32_t* AsB[2] = { sg,        sg + 4608 };
    uint32_t* BsB[2] = { sg + 9216, sg + 13824 };
    const uint32_t sbase = smem_u32(sg);

    const int tid  = threadIdx.x;
    const int brow = blockIdx.y, bcol = blockIdx.x;
    const int warp = tid >> 5, lane = tid & 31;
    const int wr = warp >> 2, wc = warp & 3;
    const int gp = lane >> 2, q = lane & 3;
    const int tr = lane & 7, lg = lane >> 3;
    const int row_off = (lg & 2) ? 8 : 0;
    const int col_off = (lg & 1) ? 4 : 0;

    float acc[4][4][4];
    #pragma unroll
    for (int mt = 0; mt < 4; mt++)
        #pragma unroll
        for (int nt = 0; nt < 4; nt++)
            #pragma unroll
            for (int r = 0; r < 4; r++) acc[mt][nt][r] = 0.f;

    const float* Ab = A  + (size_t)(brow * 128) * K;
    const float* Bb = BT + (size_t)(bcol * 128) * K;

    float4 av[4], bv[4];
    auto load_regs = [&](int kt) {
        #pragma unroll
        for (int i = 0; i < 4; i++) {
            const int u = tid + 256 * i;
            const int row = u >> 3, k4 = (u & 7) << 2;
            av[i] = *(const float4*)(Ab + (size_t)row * K + kt + k4);
            bv[i] = *(const float4*)(Bb + (size_t)row * K + kt + k4);
        }
    };
    auto store_stage = [&](int st) {
        uint32_t* As = AsB[st];
        uint32_t* Bs = BsB[st];
        #pragma unroll
        for (int i = 0; i < 4; i++) {
            const int u = tid + 256 * i;
            const int row = u >> 3, k4 = (u & 7) << 2;
            uint4 ta;
            ta.x = f2tf32(av[i].x); ta.y = f2tf32(av[i].y);
            ta.z = f2tf32(av[i].z); ta.w = f2tf32(av[i].w);
            *(uint4*)&As[row * 36 + k4] = ta;
            *(uint4*)&Bs[row * 36 + k4] = *(uint4*)&bv[i];   // pre-rounded
        }
    };

    load_regs(0);
    store_stage(0);
    __syncthreads();

    for (int kt = 0; kt < K; kt += 32) {
        const int buf = (kt >> 5) & 1;
        const bool more = (kt + 32 < K);
        if (more) load_regs(kt + 32);

        const uint32_t aoff = sbase + (buf ? 4608u * 4u : 0u);
        const uint32_t boff = sbase + 9216u * 4u + (buf ? 4608u * 4u : 0u);
        #pragma unroll
        for (int kk = 0; kk < 32; kk += 8) {
            uint32_t af[4][4], bf[4][2];
            #pragma unroll
            for (int mt = 0; mt < 4; mt++) {
                const int r = wr * 64 + mt * 16;
                const uint32_t a = aoff + ((r + tr + row_off) * 36 + kk + col_off) * 4;
                uint32_t r0, r1, r2, r3;
                LDSM_X4(r0, r1, r2, r3, a);
                af[mt][0] = r0; af[mt][1] = r2; af[mt][2] = r1; af[mt][3] = r3;
            }
            #pragma unroll
            for (int pp = 0; pp < 2; pp++) {
                const int c0 = wc * 32 + pp * 16;
                const uint32_t a = boff + ((c0 + tr + row_off) * 36 + kk + col_off) * 4;
                uint32_t r0, r1, r2, r3;
                LDSM_X4(r0, r1, r2, r3, a);
                bf[2*pp][0]   = r0; bf[2*pp][1]   = r1;
                bf[2*pp+1][0] = r2; bf[2*pp+1][1] = r3;
            }
            #pragma unroll
            for (int mt = 0; mt < 4; mt++)
                #pragma unroll
                for (int nt = 0; nt < 4; nt++)
                    mma_tf32(acc[mt][nt], af[mt], bf[nt]);
        }
        if (more) store_stage(buf ^ 1);
        __syncthreads();
    }

    #pragma unroll
    for (int mt = 0; mt < 4; mt++) {
        const int r0 = brow * 128 + wr * 64 + mt * 16 + gp;
        #pragma unroll
        for (int nt = 0; nt < 4; nt++) {
            const int c0 = bcol * 128 + wc * 32 + nt * 8 + 2 * q;
            float bb0 = 0.f, bb1 = 0.f;
            if (bias) { bb0 = bias[c0]; bb1 = bias[c0 + 1]; }
            float2 v0, v1;
            v0.x = acc[mt][nt][0] + bb0; v0.y = acc[mt][nt][1] + bb1;
            v1.x = acc[mt][nt][2] + bb0; v1.y = acc[mt][nt][3] + bb1;
            *(float2*)&C[(size_t)r0 * N + c0]       = v0;
            *(float2*)&C[(size_t)(r0 + 8) * N + c0] = v1;
        }
    }
}

// =====================================================================
// Build K/V as bf16 hi/lo, [B,H,SKV,DH].  grid (SKV, B), block 128.
// =====================================================================
__global__ void build_kv_kernel(const float* __restrict__ qkv,
                                const float* __restrict__ kcache,
                                const float* __restrict__ vcache,
                                const int* __restrict__ blockOff,
                                const float* __restrict__ cosT,
                                const float* __restrict__ sinT,
                                __nv_bfloat16* __restrict__ Kh,
                                __nv_bfloat16* __restrict__ Kl,
                                __nv_bfloat16* __restrict__ Vh,
                                __nv_bfloat16* __restrict__ Vl)
{
    const int s = blockIdx.x, b = blockIdx.y, d = threadIdx.x;
    if (s < HIST) {
        const int blk = blockOff[b * NBLK + (s >> 6)];
        const size_t src = ((size_t)(blk * BS_PAGE + (s & 63))) * H_HEADS * DHEAD;
        for (int h = 0; h < H_HEADS; h++) {
            const size_t dst = (((size_t)(b * H_HEADS + h)) * SKV + s) * DHEAD + d;
            __nv_bfloat16 hh, ll;
            split_bf16(kcache[src + h * DHEAD + d], hh, ll);
            Kh[dst] = hh; Kl[dst] = ll;
            split_bf16(vcache[src + h * DHEAD + d], hh, ll);
            Vh[dst] = hh; Vl[dst] = ll;
        }
    } else {
        const int t = b * SQ + (s - HIST);
        const int pos = s;
        const float c  = cosT[(size_t)pos * DHEAD + d];
        const float sn = sinT[(size_t)pos * DHEAD + d];
        const float* kp = qkv + (size_t)t * (3 * D_MODEL) + D_MODEL;
        const float* vp = kp + D_MODEL;
        for (int h = 0; h < H_HEADS; h++) {
            const float k1 = kp[h * DHEAD + d];
            const float rot = (d < 64) ? -kp[h * DHEAD + d + 64]
                                       :  kp[h * DHEAD + d - 64];
            const size_t dst = (((size_t)(b * H_HEADS + h)) * SKV + s) * DHEAD + d;
            __nv_bfloat16 hh, ll;
            split_bf16(k1 * c + rot * sn, hh, ll);
            Kh[dst] = hh; Kl[dst] = ll;
            split_bf16(vp[h * DHEAD + d], hh, ll);
            Vh[dst] = hh; Vl[dst] = ll;
        }
    }
}

// =====================================================================
// Flash attention v3: bf16x3, ldmatrix fragments, pre-split K/V.
// CTA: 512 threads, q-tile 128.
// smem (u32 offsets):
//   QH 0 [128][68]   QL 8704
//   KH 17408 [64][68]  KL 21760
//   VH 26112 [64][68]  VL 30464
//   SF 34816 [128][68] f32
//   PH 43520 [128][36] PL 48128
//   ST 52736 (m/l/c 128 each)
// total 53120 u32 = 212480 B
// =====================================================================
#define FL_QH 0
#define FL_QL 8704
#define FL_KH 17408
#define FL_KL 21760
#define FL_VH 26112
#define FL_VL 30464
#define FL_SF 34816
#define FL_PH 43520
#define FL_PL 48128
#define FL_ST 52736
#define FL_SMEM_BYTES (53120 * 4)

__global__ __launch_bounds__(512) void flash_v3_kernel(
    const float* __restrict__ Qg,
    const __nv_bfloat16* __restrict__ Kh,
    const __nv_bfloat16* __restrict__ Kl,
    const __nv_bfloat16* __restrict__ Vh,
    const __nv_bfloat16* __restrict__ Vl,
    const float* __restrict__ cosT,
    const float* __restrict__ sinT,
    float* __restrict__ Og)
{
    extern __shared__ uint32_t fsm[];
    uint32_t* QH = fsm + FL_QH;
    uint32_t* QL = fsm + FL_QL;
    uint32_t* KHs = fsm + FL_KH;
    uint32_t* KLs = fsm + FL_KL;
    uint32_t* VHs = fsm + FL_VH;
    uint32_t* VLs = fsm + FL_VL;
    float*    SF = (float*)(fsm + FL_SF);
    uint32_t* PH = fsm + FL_PH;
    uint32_t* PL = fsm + FL_PL;
    float* m_s = (float*)(fsm + FL_ST);
    float* l_s = m_s + 128;
    float* c_s = l_s + 128;
    const uint32_t sbase = smem_u32(fsm);

    const int bh = blockIdx.x;
    const int b = bh >> 5, h = bh & 31;
    const int q0 = blockIdx.y * 128;
    const int tid = threadIdx.x;
    const int warp = tid >> 5, lane = tid & 31;
    const int gp = lane >> 2, q = lane & 3;
    const int tr = lane & 7, lg = lane >> 3;
    const int wr = warp >> 2, wc = warp & 3;     // S phase: 4x4
    const int wor = warp >> 1, woc = warp & 1;   // PV phase: 8x2
    const int row_off = (lg & 2) ? 8 : 0;        // non-trans grouping
    const int col_off = (lg & 1) ? 4 : 0;
    const int row_off_t = (lg & 1) ? 8 : 0;      // trans grouping
    const int col_off_t = (lg & 2) ? 4 : 0;

    // ---- load Q tile + RoPE + logn + bf16 split ----
    {
        const int row = tid >> 2;
        const int d0  = (tid & 3) * 16;
        const int t   = b * SQ + q0 + row;
        const int pos = HIST + q0 + row;
        const float logn = logf((float)(pos + 1)) * INV_LN1024;
        const float* qrow = Qg + (size_t)t * (3 * D_MODEL) + h * DHEAD;
        const float* crow = cosT + (size_t)pos * DHEAD;
        const float* srow = sinT + (size_t)pos * DHEAD;
        float qa[16], qb[16], ca[16], cb[16], sa[16], sb[16];
        #pragma unroll
        for (int i = 0; i < 4; i++) {
            *(float4*)&qa[4*i] = *(const float4*)(qrow + d0 + 4*i);
            *(float4*)&qb[4*i] = *(const float4*)(qrow + d0 + 64 + 4*i);
            *(float4*)&ca[4*i] = *(const float4*)(crow + d0 + 4*i);
            *(float4*)&cb[4*i] = *(const float4*)(crow + d0 + 64 + 4*i);
            *(float4*)&sa[4*i] = *(const float4*)(srow + d0 + 4*i);
            *(float4*)&sb[4*i] = *(const float4*)(srow + d0 + 64 + 4*i);
        }
        #pragma unroll
        for (int j = 0; j < 8; j++) {
            float f0 = (qa[2*j]   * ca[2*j]   - qb[2*j]   * sa[2*j])   * logn;
            float f1 = (qa[2*j+1] * ca[2*j+1] - qb[2*j+1] * sa[2*j+1]) * logn;
            float g0 = (qb[2*j]   * cb[2*j]   + qa[2*j]   * sb[2*j])   * logn;
            float g1 = (qb[2*j+1] * cb[2*j+1] + qa[2*j+1] * sb[2*j+1]) * logn;
            __nv_bfloat16 h0, l0, h1, l1;
            split_bf16(f0, h0, l0); split_bf16(f1, h1, l1);
            QH[row * 68 + d0/2 + j] = pack2(h0, h1);
            QL[row * 68 + d0/2 + j] = pack2(l0, l1);
            split_bf16(g0, h0, l0); split_bf16(g1, h1, l1);
            QH[row * 68 + (d0 + 64)/2 + j] = pack2(h0, h1);
            QL[row * 68 + (d0 + 64)/2 + j] = pack2(l0, l1);
        }
    }
    if (tid < 128) { m_s[tid] = -1e30f; l_s[tid] = 0.f; }

    float oacc[8][4];
    #pragma unroll
    for (int nt = 0; nt < 8; nt++)
        { oacc[nt][0]=0.f; oacc[nt][1]=0.f; oacc[nt][2]=0.f; oacc[nt][3]=0.f; }

    const size_t bhofs = (size_t)bh * SKV * DHEAD;
    const int ntiles = (HIST + q0 + 128) / 64;
    __syncthreads();

    for (int kt = 0; kt < ntiles; kt++) {
        const int s0 = kt * 64;
        // ---- fill K/V tiles (pure bf16 copies, 8 u32 per thread per tile) ----
        {
            const int row = tid >> 3;
            const int c8  = (tid & 7) * 8;         // u32 col
            const size_t src = bhofs + (size_t)(s0 + row) * DHEAD + c8 * 2;
            const uint4* pkh = (const uint4*)(Kh + src);
            const uint4* pkl = (const uint4*)(Kl + src);
            const uint4* pvh = (const uint4*)(Vh + src);
            const uint4* pvl = (const uint4*)(Vl + src);
            *(uint4*)&KHs[row * 68 + c8]     = pkh[0];
            *(uint4*)&KHs[row * 68 + c8 + 4] = pkh[1];
            *(uint4*)&KLs[row * 68 + c8]     = pkl[0];
            *(uint4*)&KLs[row * 68 + c8 + 4] = pkl[1];
            *(uint4*)&VHs[row * 68 + c8]     = pvh[0];
            *(uint4*)&VHs[row * 68 + c8 + 4] = pvh[1];
            *(uint4*)&VLs[row * 68 + c8]     = pvl[0];
            *(uint4*)&VLs[row * 68 + c8 + 4] = pvl[1];
        }
        __syncthreads();

        // ---- S = Q @ K^T  (bf16x3, ldmatrix) ----
        float sacc[2][2][4];
        #pragma unroll
        for (int mt = 0; mt < 2; mt++)
            #pragma unroll
            for (int nt = 0; nt < 2; nt++)
                #pragma unroll
                for (int r = 0; r < 4; r++) sacc[mt][nt][r] = 0.f;

        #pragma unroll
        for (int ks = 0; ks < 8; ks++) {
            const int j0 = ks * 8;
            uint32_t ah[2][4], al[2][4], bhv[2][2], blv[2][2];
            #pragma unroll
            for (int mt = 0; mt < 2; mt++) {
                const int r = wr * 32 + mt * 16;
                const uint32_t base = (r + tr + row_off) * 68 + j0 + col_off;
                uint32_t r0, r1, r2, r3;
                LDSM_X4(r0, r1, r2, r3, sbase + (FL_QH + base) * 4);
                ah[mt][0] = r0; ah[mt][1] = r2; ah[mt][2] = r1; ah[mt][3] = r3;
                LDSM_X4(r0, r1, r2, r3, sbase + (FL_QL + base) * 4);
                al[mt][0] = r0; al[mt][1] = r2; al[mt][2] = r1; al[mt][3] = r3;
            }
            {
                const int c0 = wc * 16;
                const uint32_t base = (c0 + tr + row_off) * 68 + j0 + col_off;
                uint32_t r0, r1, r2, r3;
                LDSM_X4(r0, r1, r2, r3, sbase + (FL_KH + base) * 4);
                bhv[0][0] = r0; bhv[0][1] = r1; bhv[1][0] = r2; bhv[1][1] = r3;
                LDSM_X4(r0, r1, r2, r3, sbase + (FL_KL + base) * 4);
                blv[0][0] = r0; blv[0][1] = r1; blv[1][0] = r2; blv[1][1] = r3;
            }
            #pragma unroll
            for (int mt = 0; mt < 2; mt++)
                #pragma unroll
                for (int nt = 0; nt < 2; nt++) {
                    mma_bf16(sacc[mt][nt], ah[mt], bhv[nt]);
                    mma_bf16(sacc[mt][nt], ah[mt], blv[nt]);
                    mma_bf16(sacc[mt][nt], al[mt], bhv[nt]);
                }
        }

        // ---- scale + causal mask + stage to SF ----
        const bool maskt = (kt >= ntiles - 2);
        #pragma unroll
        for (int mt = 0; mt < 2; mt++) {
            const int r = wr * 32 + mt * 16 + gp;
            const int qp0 = HIST + q0 + r, qp1 = qp0 + 8;
            #pragma unroll
            for (int nt = 0; nt < 2; nt++) {
                const int cc = wc * 16 + nt * 8 + 2 * q;
                float v0 = sacc[mt][nt][0] * ATT_SCALE;
                float v1 = sacc[mt][nt][1] * ATT_SCALE;
                float v2 = sacc[mt][nt][2] * ATT_SCALE;
                float v3 = sacc[mt][nt][3] * ATT_SCALE;
                if (maskt) {
                    const int s_abs = s0 + cc;
                    if (s_abs     > qp0) v0 = -1e30f;
                    if (s_abs + 1 > qp0) v1 = -1e30f;
                    if (s_abs     > qp1) v2 = -1e30f;
                    if (s_abs + 1 > qp1) v3 = -1e30f;
                }
                SF[r * 68 + cc] = v0;       SF[r * 68 + cc + 1] = v1;
                SF[(r + 8) * 68 + cc] = v2; SF[(r + 8) * 68 + cc + 1] = v3;
            }
        }
        __syncthreads();

        // ---- online softmax (4 threads/row), write P bf16 hi/lo ----
        {
            const int row = tid >> 2, q2 = tid & 3;
            const float* prow = SF + row * 68 + q2 * 16;
            float pv[16];
            float mx = -1e30f;
            #pragma unroll
            for (int k = 0; k < 16; k++) { pv[k] = prow[k]; mx = fmaxf(mx, pv[k]); }
            mx = fmaxf(mx, __shfl_xor_sync(0xffffffffu, mx, 1));
            mx = fmaxf(mx, __shfl_xor_sync(0xffffffffu, mx, 2));
            const float m_old = m_s[row];
            const float m_new = fmaxf(m_old, mx);
            float ssum = 0.f;
            #pragma unroll
            for (int k = 0; k < 16; k++) {
                pv[k] = fast_exp(pv[k] - m_new);
                ssum += pv[k];
            }
            #pragma unroll
            for (int u = 0; u < 8; u++) {
                __nv_bfloat16 h0, l0, h1, l1;
                split_bf16(pv[2*u],   h0, l0);
                split_bf16(pv[2*u+1], h1, l1);
                PH[row * 36 + q2 * 8 + u] = pack2(h0, h1);
                PL[row * 36 + q2 * 8 + u] = pack2(l0, l1);
            }
            ssum += __shfl_xor_sync(0xffffffffu, ssum, 1);
            ssum += __shfl_xor_sync(0xffffffffu, ssum, 2);
            if (q2 == 0) {
                const float corr = fast_exp(m_old - m_new);
                l_s[row] = l_s[row] * corr + ssum;
                m_s[row] = m_new;
                c_s[row] = corr;
            }
        }
        __syncthreads();

        // ---- O = O*corr + P @ V  (bf16x3, ldmatrix) ----
        {
            const float c0 = c_s[wor * 16 + gp];
            const float c1 = c_s[wor * 16 + gp + 8];
            #pragma unroll
            for (int nt = 0; nt < 8; nt++) {
                oacc[nt][0] *= c0; oacc[nt][1] *= c0;
                oacc[nt][2] *= c1; oacc[nt][3] *= c1;
            }
        }
        #pragma unroll
        for (int js = 0; js < 4; js++) {
            const int j0 = js * 8;
            const int r = wor * 16;
            uint32_t ph[4], pl[4];
            {
                const uint32_t base = (r + tr + row_off) * 36 + j0 + col_off;
                uint32_t r0, r1, r2, r3;
                LDSM_X4(r0, r1, r2, r3, sbase + (FL_PH + base) * 4);
                ph[0] = r0; ph[1] = r2; ph[2] = r1; ph[3] = r3;
                LDSM_X4(r0, r1, r2, r3, sbase + (FL_PL + base) * 4);
                pl[0] = r0; pl[1] = r2; pl[2] = r1; pl[3] = r3;
            }
            #pragma unroll
            for (int pp = 0; pp < 4; pp++) {
                const int cu = woc * 32 + pp * 8;   // u32 col of V tile
                const uint32_t base = (js * 16 + tr + row_off_t) * 68 + cu + col_off_t;
                uint32_t r0, r1, r2, r3;
                uint32_t bvh[2][2], bvl[2][2];
                LDSM_X4_T(r0, r1, r2, r3, sbase + (FL_VH + base) * 4);
                bvh[0][0] = r0; bvh[0][1] = r1; bvh[1][0] = r2; bvh[1][1] = r3;
                LDSM_X4_T(r0, r1, r2, r3, sbase + (FL_VL + base) * 4);
                bvl[0][0] = r0; bvl[0][1] = r1; bvl[1][0] = r2; bvl[1][1] = r3;
                #pragma unroll
                for (int x = 0; x < 2; x++) {
                    const int nt = pp * 2 + x;
                    mma_bf16(oacc[nt], ph, bvh[x]);
                    mma_bf16(oacc[nt], ph, bvl[x]);
                    mma_bf16(oacc[nt], pl, bvh[x]);
                }
            }
        }
        __syncthreads();
    }

    // ---- epilogue ----
    {
        const int r = wor * 16 + gp;
        const float inv0 = 1.f / l_s[r];
        const float inv1 = 1.f / l_s[r + 8];
        const int t0 = b * SQ + q0 + r;
        #pragma unroll
        for (int nt = 0; nt < 8; nt++) {
            const int c = woc * 64 + nt * 8 + 2 * q;
            float2 w0, w1;
            w0.x = oacc[nt][0] * inv0; w0.y = oacc[nt][1] * inv0;
            w1.x = oacc[nt][2] * inv1; w1.y = oacc[nt][3] * inv1;
            *(float2*)&Og[(size_t)t0 * D_MODEL + h * DHEAD + c]       = w0;
            *(float2*)&Og[(size_t)(t0 + 8) * D_MODEL + h * DHEAD + c] = w1;
        }
    }
}

// =====================================================================
// launch
// =====================================================================
extern "C" void kernel_launch(void* const* d_in, const int* in_sizes, int n_in,
                              void* d_out, int out_size)
{
    const float* hidden  = (const float*)d_in[0];
    const float* w_qkv   = (const float*)d_in[1];
    const float* b_qkv   = (const float*)d_in[2];
    const float* w_proj  = (const float*)d_in[3];
    const float* cosT    = (const float*)d_in[4];
    const float* sinT    = (const float*)d_in[5];
    const float* kcache  = (const float*)d_in[6];
    const float* vcache  = (const float*)d_in[7];
    const int*   blkOff  = (const int*)d_in[8];
    float* out = (float*)d_out;

    float *qkv_p, *attn_p, *wqkvT, *wprojT;
    __nv_bfloat16 *kh, *kl, *vh, *vl;
    cudaGetSymbolAddress((void**)&qkv_p,  g_qkv);
    cudaGetSymbolAddress((void**)&attn_p, g_attn);
    cudaGetSymbolAddress((void**)&wqkvT,  g_wqkvT);
    cudaGetSymbolAddress((void**)&wprojT, g_wprojT);
    cudaGetSymbolAddress((void**)&kh, g_kh);
    cudaGetSymbolAddress((void**)&kl, g_kl);
    cudaGetSymbolAddress((void**)&vh, g_vh);
    cudaGetSymbolAddress((void**)&vl, g_vl);

    cudaFuncSetAttribute(tf32_gemm_ldsm_kernel,
                         cudaFuncAttributeMaxDynamicSharedMemorySize, G_SMEM_BYTES);
    cudaFuncSetAttribute(flash_v3_kernel,
                         cudaFuncAttributeMaxDynamicSharedMemorySize, FL_SMEM_BYTES);

    // 0) pre-transpose + tf32-round weights
    transpose_tf32_kernel<<<dim3(3 * D_MODEL / 32, D_MODEL / 32), dim3(32, 8)>>>(
        w_qkv, wqkvT, D_MODEL, 3 * D_MODEL);
    transpose_tf32_kernel<<<dim3(D_MODEL / 32, D_MODEL / 32), dim3(32, 8)>>>(
        w_proj, wprojT, D_MODEL, D_MODEL);

    // 1) QKV projection
    tf32_gemm_ldsm_kernel<<<dim3(3 * D_MODEL / 128, T_TOK / 128), 256, G_SMEM_BYTES>>>(
        hidden, wqkvT, b_qkv, qkv_p, T_TOK, 3 * D_MODEL, D_MODEL);

    // 2) build bf16-split K/V (cache gather + RoPE on new K)
    build_kv_kernel<<<dim3(SKV, B_SEQ), 128>>>(
        qkv_p, kcache, vcache, blkOff, cosT, sinT, kh, kl, vh, vl);

    // 3) causal flash attention (RoPE+logn on Q fused)
    flash_v3_kernel<<<dim3(B_SEQ * H_HEADS, SQ / 128), 512, FL_SMEM_BYTES>>>(
        qkv_p, kh, kl, vh, vl, cosT, sinT, attn_p);

    // 4) output projection
    tf32_gemm_ldsm_kernel<<<dim3(D_MODEL / 128, T_TOK / 128), 256, G_SMEM_BYTES>>>(
        attn_p, wprojT, nullptr, out, T_TOK, D_MODEL, D_MODEL);
}

// round 9
// speedup vs baseline: 1.9964x; 1.2913x over previous
#include <cuda_runtime.h>
#include <cuda_bf16.h>
#include <cstdint>

// ---------------- problem geometry ----------------
#define T_TOK   4096
#define D_MODEL 4096
#define H_HEADS 32
#define DHEAD   128
#define B_SEQ   4
#define SQ      1024
#define HIST    1024
#define SKV     2048
#define NBLK    32
#define BS_PAGE 64
#define ATT_SCALE  0.08838834764831845f
#define INV_LN1024 0.14426950408889634f

// ---------------- scratch ----------------
__device__ float g_qkv[50331648];            // [T, 3*D]
__device__ float g_attn[16777216];           // [T, D] (tf32-rounded by flash)
__device__ float g_hidR[16777216];           // [T, D] tf32-rounded hidden
__device__ float g_wqkvT[50331648];          // [3D, D] tf32-rounded, transposed
__device__ float g_wprojT[16777216];         // [D, D]
__device__ __nv_bfloat16 g_kh[33554432];     // [B,H,SKV,DH] hi
__device__ __nv_bfloat16 g_kl[33554432];     // lo
__device__ __nv_bfloat16 g_vh[33554432];
__device__ __nv_bfloat16 g_vl[33554432];

// ---------------- helpers ----------------
__device__ __forceinline__ uint32_t smem_u32(const void* p) {
    uint32_t a;
    asm("{ .reg .u64 t; cvta.to.shared.u64 t, %1; cvt.u32.u64 %0, t; }"
        : "=r"(a) : "l"(p));
    return a;
}
__device__ __forceinline__ uint32_t f2tf32(float f) {
    uint32_t u;
    asm("cvt.rna.tf32.f32 %0, %1;" : "=r"(u) : "f"(f));
    return u;
}
__device__ __forceinline__ uint32_t pack2(__nv_bfloat16 a, __nv_bfloat16 b) {
    __nv_bfloat162 t = __nv_bfloat162(a, b);   // a -> low 16 bits (k even)
    return *reinterpret_cast<uint32_t*>(&t);
}
__device__ __forceinline__ void split_bf16(float f, __nv_bfloat16& h, __nv_bfloat16& l) {
    h = __float2bfloat16(f);
    l = __float2bfloat16(f - __bfloat162float(h));
}
#define CP_ASYNC16(dst, src) \
    asm volatile("cp.async.ca.shared.global [%0], [%1], 16;" \
                 :: "r"(dst), "l"(src) : "memory")
#define CP_COMMIT() asm volatile("cp.async.commit_group;" ::: "memory")
#define CP_WAIT(n)  asm volatile("cp.async.wait_group %0;" :: "n"(n) : "memory")
#define LDSM_X4(R0,R1,R2,R3,A) \
    asm volatile("ldmatrix.sync.aligned.m8n8.x4.shared.b16 {%0,%1,%2,%3}, [%4];" \
                 : "=r"(R0), "=r"(R1), "=r"(R2), "=r"(R3) : "r"(A))
#define LDSM_X4_T(R0,R1,R2,R3,A) \
    asm volatile("ldmatrix.sync.aligned.m8n8.x4.trans.shared.b16 {%0,%1,%2,%3}, [%4];" \
                 : "=r"(R0), "=r"(R1), "=r"(R2), "=r"(R3) : "r"(A))
__device__ __forceinline__ void mma_bf16(float* c, const uint32_t* a, const uint32_t* b) {
    asm volatile(
        "mma.sync.aligned.m16n8k16.row.col.f32.bf16.bf16.f32 "
        "{%0,%1,%2,%3}, {%4,%5,%6,%7}, {%8,%9}, {%0,%1,%2,%3};"
        : "+f"(c[0]), "+f"(c[1]), "+f"(c[2]), "+f"(c[3])
        : "r"(a[0]), "r"(a[1]), "r"(a[2]), "r"(a[3]), "r"(b[0]), "r"(b[1]));
}
__device__ __forceinline__ void mma_tf32(float* c, const uint32_t* a, const uint32_t* b) {
    asm volatile(
        "mma.sync.aligned.m16n8k8.row.col.f32.tf32.tf32.f32 "
        "{%0,%1,%2,%3}, {%4,%5,%6,%7}, {%8,%9}, {%0,%1,%2,%3};"
        : "+f"(c[0]), "+f"(c[1]), "+f"(c[2]), "+f"(c[3])
        : "r"(a[0]), "r"(a[1]), "r"(a[2]), "r"(a[3]), "r"(b[0]), "r"(b[1]));
}
// exp(x) for x <= 0, FMA-pipe only. ~1e-7 rel err.
__device__ __forceinline__ float fast_exp(float x) {
    float y = fmaxf(x * 1.4426950408889634f, -126.f);
    float z = __fadd_rn(y, 12582912.f);
    int   n = __float_as_int(z) - 0x4B400000;
    float f = y - __fsub_rn(z, 12582912.f);
    float t = f * 0.6931471805599453f;
    float p = __fmaf_rn(t, 0.0013888889f, 0.0083333333f);
    p = __fmaf_rn(t, p, 0.0416666667f);
    p = __fmaf_rn(t, p, 0.1666666667f);
    p = __fmaf_rn(t, p, 0.5f);
    p = __fmaf_rn(t, p, 1.0f);
    p = __fmaf_rn(t, p, 1.0f);
    return p * __int_as_float((n + 127) << 23);
}

// =====================================================================
// Prep: W[K][N] fp32 -> WT[N][K] fp32 with tf32(RNA) rounding applied.
// =====================================================================
__global__ __launch_bounds__(256) void transpose_tf32_kernel(
    const float* __restrict__ W, float* __restrict__ WT, int Kd, int Nd)
{
    __shared__ float ts[32][33];
    const int n0 = blockIdx.x * 32, k0 = blockIdx.y * 32;
    const int tx = threadIdx.x, ty = threadIdx.y;
    #pragma unroll
    for (int j = ty; j < 32; j += 8)
        ts[j][tx] = W[(size_t)(k0 + j) * Nd + n0 + tx];
    __syncthreads();
    #pragma unroll
    for (int j = ty; j < 32; j += 8)
        WT[(size_t)(n0 + j) * Kd + k0 + tx] = __uint_as_float(f2tf32(ts[tx][j]));
}

// =====================================================================
// Prep: elementwise tf32(RNA) round.  n multiple of 1024.
// =====================================================================
__global__ __launch_bounds__(256) void round_tf32_kernel(
    const float* __restrict__ X, float* __restrict__ Y)
{
    const int i = (blockIdx.x * 256 + threadIdx.x) * 4;
    const float4 v = *(const float4*)(X + i);
    uint4 u;
    u.x = f2tf32(v.x); u.y = f2tf32(v.y); u.z = f2tf32(v.z); u.w = f2tf32(v.w);
    *(uint4*)(Y + i) = u;
}

// =====================================================================
// TF32 GEMM, cp.async double-buffered: C[M,N] = A[M,K] @ B[K,N] (+bias)
// A pre-rounded tf32 (fp32 storage); B pre-transposed+rounded BT[N][K].
// 128x128x32 tile, 8 warps (2x4), warp tile 64x32, m16n8k8 tf32.
// smem (u32): As[2][128][36], Bs[2][128][36]  -> 73728 B
// =====================================================================
#define G_SMEM_BYTES (18432 * 4)

__global__ __launch_bounds__(256, 2) void tf32_gemm_cp_kernel(
    const float* __restrict__ A, const float* __restrict__ BT,
    const float* __restrict__ bias, float* __restrict__ C,
    int M, int N, int K)
{
    extern __shared__ uint32_t sg[];
    const uint32_t sbase = smem_u32(sg);

    const int tid  = threadIdx.x;
    const int brow = blockIdx.y, bcol = blockIdx.x;
    const int warp = tid >> 5, lane = tid & 31;
    const int wr = warp >> 2, wc = warp & 3;
    const int gp = lane >> 2, q = lane & 3;
    const int tr = lane & 7, lg = lane >> 3;
    const int row_off = (lg & 2) ? 8 : 0;
    const int col_off = (lg & 1) ? 4 : 0;

    float acc[4][4][4];
    #pragma unroll
    for (int mt = 0; mt < 4; mt++)
        #pragma unroll
        for (int nt = 0; nt < 4; nt++)
            #pragma unroll
            for (int r = 0; r < 4; r++) acc[mt][nt][r] = 0.f;

    const float* Ab = A  + (size_t)(brow * 128) * K;
    const float* Bb = BT + (size_t)(bcol * 128) * K;

    auto fill = [&](int st, int kt) {
        const uint32_t aoff = sbase + (st * 4608) * 4;
        const uint32_t boff = sbase + (9216 + st * 4608) * 4;
        #pragma unroll
        for (int i = 0; i < 4; i++) {
            const int u = tid + 256 * i;
            const int r = u >> 3, kq = (u & 7) << 2;
            CP_ASYNC16(aoff + (r * 36 + kq) * 4, Ab + (size_t)r * K + kt + kq);
            CP_ASYNC16(boff + (r * 36 + kq) * 4, Bb + (size_t)r * K + kt + kq);
        }
        CP_COMMIT();
    };

    fill(0, 0);

    for (int kt = 0; kt < K; kt += 32) {
        const int buf = (kt >> 5) & 1;
        const bool more = (kt + 32 < K);
        if (more) { fill(buf ^ 1, kt + 32); CP_WAIT(1); }
        else      { CP_WAIT(0); }
        __syncthreads();

        const uint32_t aoff = sbase + (buf * 4608) * 4;
        const uint32_t boff = sbase + ((9216 + buf * 4608)) * 4;
        #pragma unroll
        for (int kk = 0; kk < 32; kk += 8) {
            uint32_t af[4][4], bf[4][2];
            #pragma unroll
            for (int mt = 0; mt < 4; mt++) {
                const int r = wr * 64 + mt * 16;
                const uint32_t a = aoff + ((r + tr + row_off) * 36 + kk + col_off) * 4;
                uint32_t r0, r1, r2, r3;
                LDSM_X4(r0, r1, r2, r3, a);
                af[mt][0] = r0; af[mt][1] = r2; af[mt][2] = r1; af[mt][3] = r3;
            }
            #pragma unroll
            for (int pp = 0; pp < 2; pp++) {
                const int c0 = wc * 32 + pp * 16;
                const uint32_t a = boff + ((c0 + tr + row_off) * 36 + kk + col_off) * 4;
                uint32_t r0, r1, r2, r3;
                LDSM_X4(r0, r1, r2, r3, a);
                bf[2*pp][0]   = r0; bf[2*pp][1]   = r1;
                bf[2*pp+1][0] = r2; bf[2*pp+1][1] = r3;
            }
            #pragma unroll
            for (int mt = 0; mt < 4; mt++)
                #pragma unroll
                for (int nt = 0; nt < 4; nt++)
                    mma_tf32(acc[mt][nt], af[mt], bf[nt]);
        }
        __syncthreads();
    }

    #pragma unroll
    for (int mt = 0; mt < 4; mt++) {
        const int r0 = brow * 128 + wr * 64 + mt * 16 + gp;
        #pragma unroll
        for (int nt = 0; nt < 4; nt++) {
            const int c0 = bcol * 128 + wc * 32 + nt * 8 + 2 * q;
            float bb0 = 0.f, bb1 = 0.f;
            if (bias) { bb0 = bias[c0]; bb1 = bias[c0 + 1]; }
            float2 v0, v1;
            v0.x = acc[mt][nt][0] + bb0; v0.y = acc[mt][nt][1] + bb1;
            v1.x = acc[mt][nt][2] + bb0; v1.y = acc[mt][nt][3] + bb1;
            *(float2*)&C[(size_t)r0 * N + c0]       = v0;
            *(float2*)&C[(size_t)(r0 + 8) * N + c0] = v1;
        }
    }
}

// =====================================================================
// Build K/V as bf16 hi/lo, [B,H,SKV,DH].  grid (SKV, B), block 128.
// =====================================================================
__global__ void build_kv_kernel(const float* __restrict__ qkv,
                                const float* __restrict__ kcache,
                                const float* __restrict__ vcache,
                                const int* __restrict__ blockOff,
                                const float* __restrict__ cosT,
                                const float* __restrict__ sinT,
                                __nv_bfloat16* __restrict__ Kh,
                                __nv_bfloat16* __restrict__ Kl,
                                __nv_bfloat16* __restrict__ Vh,
                                __nv_bfloat16* __restrict__ Vl)
{
    const int s = blockIdx.x, b = blockIdx.y, d = threadIdx.x;
    if (s < HIST) {
        const int blk = blockOff[b * NBLK + (s >> 6)];
        const size_t src = ((size_t)(blk * BS_PAGE + (s & 63))) * H_HEADS * DHEAD;
        for (int h = 0; h < H_HEADS; h++) {
            const size_t dst = (((size_t)(b * H_HEADS + h)) * SKV + s) * DHEAD + d;
            __nv_bfloat16 hh, ll;
            split_bf16(kcache[src + h * DHEAD + d], hh, ll);
            Kh[dst] = hh; Kl[dst] = ll;
            split_bf16(vcache[src + h * DHEAD + d], hh, ll);
            Vh[dst] = hh; Vl[dst] = ll;
        }
    } else {
        const int t = b * SQ + (s - HIST);
        const int pos = s;
        const float c  = cosT[(size_t)pos * DHEAD + d];
        const float sn = sinT[(size_t)pos * DHEAD + d];
        const float* kp = qkv + (size_t)t * (3 * D_MODEL) + D_MODEL;
        const float* vp = kp + D_MODEL;
        for (int h = 0; h < H_HEADS; h++) {
            const float k1 = kp[h * DHEAD + d];
            const float rot = (d < 64) ? -kp[h * DHEAD + d + 64]
                                       :  kp[h * DHEAD + d - 64];
            const size_t dst = (((size_t)(b * H_HEADS + h)) * SKV + s) * DHEAD + d;
            __nv_bfloat16 hh, ll;
            split_bf16(k1 * c + rot * sn, hh, ll);
            Kh[dst] = hh; Kl[dst] = ll;
            split_bf16(vp[h * DHEAD + d], hh, ll);
            Vh[dst] = hh; Vl[dst] = ll;
        }
    }
}

// =====================================================================
// Flash attention v3: bf16x3, ldmatrix fragments, pre-split K/V,
// cp.async tile fills, tf32-rounded output (feeds GEMM2 A directly).
// CTA: 512 threads, q-tile 128.
// =====================================================================
#define FL_QH 0
#define FL_QL 8704
#define FL_KH 17408
#define FL_KL 21760
#define FL_VH 26112
#define FL_VL 30464
#define FL_SF 34816
#define FL_PH 43520
#define FL_PL 48128
#define FL_ST 52736
#define FL_SMEM_BYTES (53120 * 4)

__global__ __launch_bounds__(512) void flash_v3_kernel(
    const float* __restrict__ Qg,
    const __nv_bfloat16* __restrict__ Kh,
    const __nv_bfloat16* __restrict__ Kl,
    const __nv_bfloat16* __restrict__ Vh,
    const __nv_bfloat16* __restrict__ Vl,
    const float* __restrict__ cosT,
    const float* __restrict__ sinT,
    float* __restrict__ Og)
{
    extern __shared__ uint32_t fsm[];
    uint32_t* QH = fsm + FL_QH;
    uint32_t* QL = fsm + FL_QL;
    float*    SF = (float*)(fsm + FL_SF);
    uint32_t* PH = fsm + FL_PH;
    uint32_t* PL = fsm + FL_PL;
    float* m_s = (float*)(fsm + FL_ST);
    float* l_s = m_s + 128;
    float* c_s = l_s + 128;
    const uint32_t sbase = smem_u32(fsm);

    const int bh = blockIdx.x;
    const int b = bh >> 5, h = bh & 31;
    const int q0 = blockIdx.y * 128;
    const int tid = threadIdx.x;
    const int warp = tid >> 5, lane = tid & 31;
    const int gp = lane >> 2, q = lane & 3;
    const int tr = lane & 7, lg = lane >> 3;
    const int wr = warp >> 2, wc = warp & 3;     // S phase: 4x4
    const int wor = warp >> 1, woc = warp & 1;   // PV phase: 8x2
    const int row_off = (lg & 2) ? 8 : 0;        // non-trans grouping
    const int col_off = (lg & 1) ? 4 : 0;
    const int row_off_t = (lg & 1) ? 8 : 0;      // trans grouping
    const int col_off_t = (lg & 2) ? 4 : 0;

    // ---- load Q tile + RoPE + logn + bf16 split ----
    {
        const int row = tid >> 2;
        const int d0  = (tid & 3) * 16;
        const int t   = b * SQ + q0 + row;
        const int pos = HIST + q0 + row;
        const float logn = logf((float)(pos + 1)) * INV_LN1024;
        const float* qrow = Qg + (size_t)t * (3 * D_MODEL) + h * DHEAD;
        const float* crow = cosT + (size_t)pos * DHEAD;
        const float* srow = sinT + (size_t)pos * DHEAD;
        float qa[16], qb[16], ca[16], cb[16], sa[16], sb[16];
        #pragma unroll
        for (int i = 0; i < 4; i++) {
            *(float4*)&qa[4*i] = *(const float4*)(qrow + d0 + 4*i);
            *(float4*)&qb[4*i] = *(const float4*)(qrow + d0 + 64 + 4*i);
            *(float4*)&ca[4*i] = *(const float4*)(crow + d0 + 4*i);
            *(float4*)&cb[4*i] = *(const float4*)(crow + d0 + 64 + 4*i);
            *(float4*)&sa[4*i] = *(const float4*)(srow + d0 + 4*i);
            *(float4*)&sb[4*i] = *(const float4*)(srow + d0 + 64 + 4*i);
        }
        #pragma unroll
        for (int j = 0; j < 8; j++) {
            float f0 = (qa[2*j]   * ca[2*j]   - qb[2*j]   * sa[2*j])   * logn;
            float f1 = (qa[2*j+1] * ca[2*j+1] - qb[2*j+1] * sa[2*j+1]) * logn;
            float g0 = (qb[2*j]   * cb[2*j]   + qa[2*j]   * sb[2*j])   * logn;
            float g1 = (qb[2*j+1] * cb[2*j+1] + qa[2*j+1] * sb[2*j+1]) * logn;
            __nv_bfloat16 h0, l0, h1, l1;
            split_bf16(f0, h0, l0); split_bf16(f1, h1, l1);
            QH[row * 68 + d0/2 + j] = pack2(h0, h1);
            QL[row * 68 + d0/2 + j] = pack2(l0, l1);
            split_bf16(g0, h0, l0); split_bf16(g1, h1, l1);
            QH[row * 68 + (d0 + 64)/2 + j] = pack2(h0, h1);
            QL[row * 68 + (d0 + 64)/2 + j] = pack2(l0, l1);
        }
    }
    if (tid < 128) { m_s[tid] = -1e30f; l_s[tid] = 0.f; }

    float oacc[8][4];
    #pragma unroll
    for (int nt = 0; nt < 8; nt++)
        { oacc[nt][0]=0.f; oacc[nt][1]=0.f; oacc[nt][2]=0.f; oacc[nt][3]=0.f; }

    const size_t bhofs = (size_t)bh * SKV * DHEAD;
    const int ntiles = (HIST + q0 + 128) / 64;
    __syncthreads();

    for (int kt = 0; kt < ntiles; kt++) {
        const int s0 = kt * 64;
        // ---- fill K/V tiles via cp.async (pure bf16 copies) ----
        {
            const int row = tid >> 3;
            const int c8  = (tid & 7) * 8;         // u32 col
            const size_t src = bhofs + (size_t)(s0 + row) * DHEAD + c8 * 2;
            const uint32_t drow = (row * 68 + c8) * 4;
            CP_ASYNC16(sbase + (FL_KH) * 4 + drow,      Kh + src);
            CP_ASYNC16(sbase + (FL_KH + 4) * 4 + drow,  Kh + src + 8);
            CP_ASYNC16(sbase + (FL_KL) * 4 + drow,      Kl + src);
            CP_ASYNC16(sbase + (FL_KL + 4) * 4 + drow,  Kl + src + 8);
            CP_ASYNC16(sbase + (FL_VH) * 4 + drow,      Vh + src);
            CP_ASYNC16(sbase + (FL_VH + 4) * 4 + drow,  Vh + src + 8);
            CP_ASYNC16(sbase + (FL_VL) * 4 + drow,      Vl + src);
            CP_ASYNC16(sbase + (FL_VL + 4) * 4 + drow,  Vl + src + 8);
            CP_COMMIT();
            CP_WAIT(0);
        }
        __syncthreads();

        // ---- S = Q @ K^T  (bf16x3, ldmatrix) ----
        float sacc[2][2][4];
        #pragma unroll
        for (int mt = 0; mt < 2; mt++)
            #pragma unroll
            for (int nt = 0; nt < 2; nt++)
                #pragma unroll
                for (int r = 0; r < 4; r++) sacc[mt][nt][r] = 0.f;

        #pragma unroll
        for (int ks = 0; ks < 8; ks++) {
            const int j0 = ks * 8;
            uint32_t ah[2][4], al[2][4], bhv[2][2], blv[2][2];
            #pragma unroll
            for (int mt = 0; mt < 2; mt++) {
                const int r = wr * 32 + mt * 16;
                const uint32_t base = (r + tr + row_off) * 68 + j0 + col_off;
                uint32_t r0, r1, r2, r3;
                LDSM_X4(r0, r1, r2, r3, sbase + (FL_QH + base) * 4);
                ah[mt][0] = r0; ah[mt][1] = r2; ah[mt][2] = r1; ah[mt][3] = r3;
                LDSM_X4(r0, r1, r2, r3, sbase + (FL_QL + base) * 4);
                al[mt][0] = r0; al[mt][1] = r2; al[mt][2] = r1; al[mt][3] = r3;
            }
            {
                const int c0 = wc * 16;
                const uint32_t base = (c0 + tr + row_off) * 68 + j0 + col_off;
                uint32_t r0, r1, r2, r3;
                LDSM_X4(r0, r1, r2, r3, sbase + (FL_KH + base) * 4);
                bhv[0][0] = r0; bhv[0][1] = r1; bhv[1][0] = r2; bhv[1][1] = r3;
                LDSM_X4(r0, r1, r2, r3, sbase + (FL_KL + base) * 4);
                blv[0][0] = r0; blv[0][1] = r1; blv[1][0] = r2; blv[1][1] = r3;
            }
            #pragma unroll
            for (int mt = 0; mt < 2; mt++)
                #pragma unroll
                for (int nt = 0; nt < 2; nt++) {
                    mma_bf16(sacc[mt][nt], ah[mt], bhv[nt]);
                    mma_bf16(sacc[mt][nt], ah[mt], blv[nt]);
                    mma_bf16(sacc[mt][nt], al[mt], bhv[nt]);
                }
        }

        // ---- scale + causal mask + stage to SF ----
        const bool maskt = (kt >= ntiles - 2);
        #pragma unroll
        for (int mt = 0; mt < 2; mt++) {
            const int r = wr * 32 + mt * 16 + gp;
            const int qp0 = HIST + q0 + r, qp1 = qp0 + 8;
            #pragma unroll
            for (int nt = 0; nt < 2; nt++) {
                const int cc = wc * 16 + nt * 8 + 2 * q;
                float v0 = sacc[mt][nt][0] * ATT_SCALE;
                float v1 = sacc[mt][nt][1] * ATT_SCALE;
                float v2 = sacc[mt][nt][2] * ATT_SCALE;
                float v3 = sacc[mt][nt][3] * ATT_SCALE;
                if (maskt) {
                    const int s_abs = s0 + cc;
                    if (s_abs     > qp0) v0 = -1e30f;
                    if (s_abs + 1 > qp0) v1 = -1e30f;
                    if (s_abs     > qp1) v2 = -1e30f;
                    if (s_abs + 1 > qp1) v3 = -1e30f;
                }
                SF[r * 68 + cc] = v0;       SF[r * 68 + cc + 1] = v1;
                SF[(r + 8) * 68 + cc] = v2; SF[(r + 8) * 68 + cc + 1] = v3;
            }
        }
        __syncthreads();

        // ---- online softmax (4 threads/row), write P bf16 hi/lo ----
        {
            const int row = tid >> 2, q2 = tid & 3;
            const float* prow = SF + row * 68 + q2 * 16;
            float pv[16];
            float mx = -1e30f;
            #pragma unroll
            for (int k = 0; k < 16; k++) { pv[k] = prow[k]; mx = fmaxf(mx, pv[k]); }
            mx = fmaxf(mx, __shfl_xor_sync(0xffffffffu, mx, 1));
            mx = fmaxf(mx, __shfl_xor_sync(0xffffffffu, mx, 2));
            const float m_old = m_s[row];
            const float m_new = fmaxf(m_old, mx);
            float ssum = 0.f;
            #pragma unroll
            for (int k = 0; k < 16; k++) {
                pv[k] = fast_exp(pv[k] - m_new);
                ssum += pv[k];
            }
            #pragma unroll
            for (int u = 0; u < 8; u++) {
                __nv_bfloat16 h0, l0, h1, l1;
                split_bf16(pv[2*u],   h0, l0);
                split_bf16(pv[2*u+1], h1, l1);
                PH[row * 36 + q2 * 8 + u] = pack2(h0, h1);
                PL[row * 36 + q2 * 8 + u] = pack2(l0, l1);
            }
            ssum += __shfl_xor_sync(0xffffffffu, ssum, 1);
            ssum += __shfl_xor_sync(0xffffffffu, ssum, 2);
            if (q2 == 0) {
                const float corr = fast_exp(m_old - m_new);
                l_s[row] = l_s[row] * corr + ssum;
                m_s[row] = m_new;
                c_s[row] = corr;
            }
        }
        __syncthreads();

        // ---- O = O*corr + P @ V  (bf16x3, ldmatrix) ----
        {
            const float c0 = c_s[wor * 16 + gp];
            const float c1 = c_s[wor * 16 + gp + 8];
            #pragma unroll
            for (int nt = 0; nt < 8; nt++) {
                oacc[nt][0] *= c0; oacc[nt][1] *= c0;
                oacc[nt][2] *= c1; oacc[nt][3] *= c1;
            }
        }
        #pragma unroll
        for (int js = 0; js < 4; js++) {
            const int j0 = js * 8;
            const int r = wor * 16;
            uint32_t ph[4], pl[4];
            {
                const uint32_t base = (r + tr + row_off) * 36 + j0 + col_off;
                uint32_t r0, r1, r2, r3;
                LDSM_X4(r0, r1, r2, r3, sbase + (FL_PH + base) * 4);
                ph[0] = r0; ph[1] = r2; ph[2] = r1; ph[3] = r3;
                LDSM_X4(r0, r1, r2, r3, sbase + (FL_PL + base) * 4);
                pl[0] = r0; pl[1] = r2; pl[2] = r1; pl[3] = r3;
            }
            #pragma unroll
            for (int pp = 0; pp < 4; pp++) {
                const int cu = woc * 32 + pp * 8;   // u32 col of V tile
                const uint32_t base = (js * 16 + tr + row_off_t) * 68 + cu + col_off_t;
                uint32_t r0, r1, r2, r3;
                uint32_t bvh[2][2], bvl[2][2];
                LDSM_X4_T(r0, r1, r2, r3, sbase + (FL_VH + base) * 4);
                bvh[0][0] = r0; bvh[0][1] = r1; bvh[1][0] = r2; bvh[1][1] = r3;
                LDSM_X4_T(r0, r1, r2, r3, sbase + (FL_VL + base) * 4);
                bvl[0][0] = r0; bvl[0][1] = r1; bvl[1][0] = r2; bvl[1][1] = r3;
                #pragma unroll
                for (int x = 0; x < 2; x++) {
                    const int nt = pp * 2 + x;
                    mma_bf16(oacc[nt], ph, bvh[x]);
                    mma_bf16(oacc[nt], ph, bvl[x]);
                    mma_bf16(oacc[nt], pl, bvh[x]);
                }
            }
        }
        __syncthreads();
    }

    // ---- epilogue (tf32-rounded: feeds GEMM2's A operand directly) ----
    {
        const int r = wor * 16 + gp;
        const float inv0 = 1.f / l_s[r];
        const float inv1 = 1.f / l_s[r + 8];
        const int t0 = b * SQ + q0 + r;
        #pragma unroll
        for (int nt = 0; nt < 8; nt++) {
            const int c = woc * 64 + nt * 8 + 2 * q;
            uint2 w0, w1;
            w0.x = f2tf32(oacc[nt][0] * inv0); w0.y = f2tf32(oacc[nt][1] * inv0);
            w1.x = f2tf32(oacc[nt][2] * inv1); w1.y = f2tf32(oacc[nt][3] * inv1);
            *(uint2*)&Og[(size_t)t0 * D_MODEL + h * DHEAD + c]       = w0;
            *(uint2*)&Og[(size_t)(t0 + 8) * D_MODEL + h * DHEAD + c] = w1;
        }
    }
}

// =====================================================================
// launch
// =====================================================================
extern "C" void kernel_launch(void* const* d_in, const int* in_sizes, int n_in,
                              void* d_out, int out_size)
{
    const float* hidden  = (const float*)d_in[0];
    const float* w_qkv   = (const float*)d_in[1];
    const float* b_qkv   = (const float*)d_in[2];
    const float* w_proj  = (const float*)d_in[3];
    const float* cosT    = (const float*)d_in[4];
    const float* sinT    = (const float*)d_in[5];
    const float* kcache  = (const float*)d_in[6];
    const float* vcache  = (const float*)d_in[7];
    const int*   blkOff  = (const int*)d_in[8];
    float* out = (float*)d_out;

    float *qkv_p, *attn_p, *hidR, *wqkvT, *wprojT;
    __nv_bfloat16 *kh, *kl, *vh, *vl;
    cudaGetSymbolAddress((void**)&qkv_p,  g_qkv);
    cudaGetSymbolAddress((void**)&attn_p, g_attn);
    cudaGetSymbolAddress((void**)&hidR,   g_hidR);
    cudaGetSymbolAddress((void**)&wqkvT,  g_wqkvT);
    cudaGetSymbolAddress((void**)&wprojT, g_wprojT);
    cudaGetSymbolAddress((void**)&kh, g_kh);
    cudaGetSymbolAddress((void**)&kl, g_kl);
    cudaGetSymbolAddress((void**)&vh, g_vh);
    cudaGetSymbolAddress((void**)&vl, g_vl);

    cudaFuncSetAttribute(tf32_gemm_cp_kernel,
                         cudaFuncAttributeMaxDynamicSharedMemorySize, G_SMEM_BYTES);
    cudaFuncSetAttribute(flash_v3_kernel,
                         cudaFuncAttributeMaxDynamicSharedMemorySize, FL_SMEM_BYTES);

    // 0) prep: transpose+round weights, round hidden
    transpose_tf32_kernel<<<dim3(3 * D_MODEL / 32, D_MODEL / 32), dim3(32, 8)>>>(
        w_qkv, wqkvT, D_MODEL, 3 * D_MODEL);
    transpose_tf32_kernel<<<dim3(D_MODEL / 32, D_MODEL / 32), dim3(32, 8)>>>(
        w_proj, wprojT, D_MODEL, D_MODEL);
    round_tf32_kernel<<<T_TOK * D_MODEL / 1024, 256>>>(hidden, hidR);

    // 1) QKV projection
    tf32_gemm_cp_kernel<<<dim3(3 * D_MODEL / 128, T_TOK / 128), 256, G_SMEM_BYTES>>>(
        hidR, wqkvT, b_qkv, qkv_p, T_TOK, 3 * D_MODEL, D_MODEL);

    // 2) build bf16-split K/V (cache gather + RoPE on new K)
    build_kv_kernel<<<dim3(SKV, B_SEQ), 128>>>(
        qkv_p, kcache, vcache, blkOff, cosT, sinT, kh, kl, vh, vl);

    // 3) causal flash attention (RoPE+logn on Q fused; rounded output)
    flash_v3_kernel<<<dim3(B_SEQ * H_HEADS, SQ / 128), 512, FL_SMEM_BYTES>>>(
        qkv_p, kh, kl, vh, vl, cosT, sinT, attn_p);

    // 4) output projection
    tf32_gemm_cp_kernel<<<dim3(D_MODEL / 128, T_TOK / 128), 256, G_SMEM_BYTES>>>(
        attn_p, wprojT, nullptr, out, T_TOK, D_MODEL, D_MODEL);
}